// round 12
// baseline (speedup 1.0000x reference)
#include <cuda_runtime.h>
#include <cuda_bf16.h>
#include <math.h>
#include <cstdint>

#define BB 2
#define LL 2048
#define DD 1024
#define HH 16
#define DH 64
#define ML (BB*LL)          // 4096 rows
#define NPERS 296           // persistent CTAs (148 SMs x 2)

// ---------------------------------------------------------------------------
// Scratch (allocation-free rule: device globals)
// ---------------------------------------------------------------------------
__device__ float g_qkv[ML * 3 * DD];        // [b,l,3,h,dh] fp32 (QKV gemm out)

// bf16 flash operands (written by rope kernel)
__device__ __nv_bfloat16 g_qh[BB*HH*LL*DH], g_ql[BB*HH*LL*DH];   // [bh][l][d], pre-scaled 1/8
__device__ __nv_bfloat16 g_kh[BB*HH*LL*DH], g_kl[BB*HH*LL*DH];   // [bh][l][d]
__device__ __nv_bfloat16 g_vth[BB*HH*DH*LL], g_vtl[BB*HH*DH*LL]; // [bh][d][l]

// bf16 split operands for mma GEMMs
__device__ __nv_bfloat16 g_xh[ML * DD],      g_xl[ML * DD];
__device__ __nv_bfloat16 g_wqh[3 * DD * DD], g_wql[3 * DD * DD];
__device__ __nv_bfloat16 g_woh[DD * DD],     g_wol[DD * DD];
__device__ __nv_bfloat16 g_ah[ML * DD],      g_al[ML * DD];      // flash out hi/lo

// ---------------------------------------------------------------------------
// PTX helpers (sm_100-safe)
// ---------------------------------------------------------------------------
__device__ __forceinline__ uint32_t smem_u32(const void* p) {
    uint32_t a;
    asm("{ .reg .u64 t; cvta.to.shared.u64 t, %1; cvt.u32.u64 %0, t; }" : "=r"(a) : "l"(p));
    return a;
}
#define CP_ASYNC16(dst, src) \
    asm volatile("cp.async.cg.shared.global [%0], [%1], 16;" :: "r"(dst), "l"(src))
#define CP_COMMIT()  asm volatile("cp.async.commit_group;")
#define CP_WAIT0()   asm volatile("cp.async.wait_group 0;" ::: "memory")
#define CP_WAIT1()   asm volatile("cp.async.wait_group 1;" ::: "memory")

__device__ __forceinline__ void ldsm_x4(uint32_t* r, uint32_t addr) {
    asm volatile("ldmatrix.sync.aligned.m8n8.x4.shared.b16 {%0,%1,%2,%3}, [%4];"
                 : "=r"(r[0]), "=r"(r[1]), "=r"(r[2]), "=r"(r[3]) : "r"(addr));
}
__device__ __forceinline__ void mma_bf16(float* d, const uint32_t* a,
                                         uint32_t b0, uint32_t b1) {
    asm volatile(
        "mma.sync.aligned.m16n8k16.row.col.f32.bf16.bf16.f32 "
        "{%0,%1,%2,%3}, {%4,%5,%6,%7}, {%8,%9}, {%0,%1,%2,%3};"
        : "+f"(d[0]), "+f"(d[1]), "+f"(d[2]), "+f"(d[3])
        : "r"(a[0]), "r"(a[1]), "r"(a[2]), "r"(a[3]), "r"(b0), "r"(b1));
}

__device__ __forceinline__ void split1(float x, __nv_bfloat16& h, __nv_bfloat16& l) {
    h = __float2bfloat16_rn(x);
    l = __float2bfloat16_rn(x - __bfloat162float(h));
}
__device__ __forceinline__ uint32_t pack_bf16(float x, float y) {
    __nv_bfloat162 t;
    t.x = __float2bfloat16_rn(x);
    t.y = __float2bfloat16_rn(y);
    return *reinterpret_cast<uint32_t*>(&t);
}

// ---------------------------------------------------------------------------
// Split fp32 -> bf16 hi/lo
// ---------------------------------------------------------------------------
__global__ __launch_bounds__(256) void split_kernel(
    const float* __restrict__ src, __nv_bfloat16* __restrict__ hi,
    __nv_bfloat16* __restrict__ lo, int n4)
{
    int i = blockIdx.x * blockDim.x + threadIdx.x;
    if (i >= n4) return;
    float4 v = reinterpret_cast<const float4*>(src)[i];
    __nv_bfloat162 hh0, hh1, ll0, ll1;
    split1(v.x, hh0.x, ll0.x); split1(v.y, hh0.y, ll0.y);
    split1(v.z, hh1.x, ll1.x); split1(v.w, hh1.y, ll1.y);
    reinterpret_cast<__nv_bfloat162*>(hi)[i * 2]     = hh0;
    reinterpret_cast<__nv_bfloat162*>(hi)[i * 2 + 1] = hh1;
    reinterpret_cast<__nv_bfloat162*>(lo)[i * 2]     = ll0;
    reinterpret_cast<__nv_bfloat162*>(lo)[i * 2 + 1] = ll1;
}

// ---------------------------------------------------------------------------
// mma.sync GEMM: C[M,N] = A[M,K] @ W[N,K]^T via bf16x3.
// Persistent CTAs: each CTA loops over 128x128 tiles (stride gridDim.x),
// eliminating wave-quantization tail. 512 threads, 16 warps 4x4.
// ---------------------------------------------------------------------------
#define KC 32
#define ROWB 80
#define TILE_B (128 * ROWB)
#define BUF_B  (4 * TILE_B)
#define GEMM_SMEM_DYN (2 * BUF_B)

__global__ __launch_bounds__(512, 2) void gemm_mma_kernel(
    const __nv_bfloat16* __restrict__ Ah, const __nv_bfloat16* __restrict__ Al,
    const __nv_bfloat16* __restrict__ Wh, const __nv_bfloat16* __restrict__ Wl,
    float* __restrict__ C, int M, int N, int K)
{
    extern __shared__ uint8_t sm8[];
    const uint32_t sbase = smem_u32(sm8);

    const int tid  = threadIdx.x;
    const int wid  = tid >> 5;
    const int lane = tid & 31;
    const int wm = (wid & 3) * 32;
    const int wn = (wid >> 2) * 32;

    const uint32_t aOff = (uint32_t)((wm + (lane & 15)) * ROWB + (lane >> 4) * 16);
    const uint32_t bOff = (uint32_t)((wn + (lane & 7) + ((lane >> 4) << 3)) * ROWB
                                     + ((lane >> 3) & 1) * 16);
    const int nc = K / KC;
    const int ntn = N >> 7;
    const int ntiles = (M >> 7) * ntn;

    for (int tile = blockIdx.x; tile < ntiles; tile += gridDim.x) {
        const int m0 = (tile / ntn) * 128;
        const int n0 = (tile % ntn) * 128;

        float acc[2][4][4];
#pragma unroll
        for (int i = 0; i < 2; i++)
#pragma unroll
            for (int j = 0; j < 4; j++)
#pragma unroll
                for (int q = 0; q < 4; q++) acc[i][j][q] = 0.f;

        auto issue_loads = [&](int c, int buf) {
            const int kc = c * KC;
            const uint32_t dstb = sbase + buf * BUF_B;
#pragma unroll
            for (int it = 0; it < 4; it++) {
                int op = tid + it * 512;
                int t = op >> 9;
                int r = (op >> 2) & 127;
                int p = op & 3;
                const __nv_bfloat16* srcp;
                if (t == 0)      srcp = Ah + (size_t)(m0 + r) * K + kc + p * 8;
                else if (t == 1) srcp = Al + (size_t)(m0 + r) * K + kc + p * 8;
                else if (t == 2) srcp = Wh + (size_t)(n0 + r) * K + kc + p * 8;
                else             srcp = Wl + (size_t)(n0 + r) * K + kc + p * 8;
                CP_ASYNC16(dstb + t * TILE_B + r * ROWB + p * 16, srcp);
            }
            CP_COMMIT();
        };

        issue_loads(0, 0);

        for (int c = 0; c < nc; c++) {
            if (c + 1 < nc) { issue_loads(c + 1, (c + 1) & 1); CP_WAIT1(); }
            else            { CP_WAIT0(); }
            __syncthreads();

            const uint32_t dstb = sbase + (c & 1) * BUF_B;
#pragma unroll
            for (int step = 0; step < 2; step++) {
                uint32_t aFh[2][4], aFl[2][4];
#pragma unroll
                for (int mt = 0; mt < 2; mt++) {
                    ldsm_x4(aFh[mt], dstb + aOff + mt * 16 * ROWB + step * 32);
                    ldsm_x4(aFl[mt], dstb + TILE_B + aOff + mt * 16 * ROWB + step * 32);
                }
                uint32_t bFh[8], bFl[8];
#pragma unroll
                for (int nt2 = 0; nt2 < 2; nt2++) {
                    ldsm_x4(bFh + nt2 * 4, dstb + 2 * TILE_B + bOff + nt2 * 16 * ROWB + step * 32);
                    ldsm_x4(bFl + nt2 * 4, dstb + 3 * TILE_B + bOff + nt2 * 16 * ROWB + step * 32);
                }
#pragma unroll
                for (int mt = 0; mt < 2; mt++)
#pragma unroll
                    for (int nt = 0; nt < 4; nt++) {
                        int bi = (nt >> 1) * 4 + (nt & 1) * 2;
                        mma_bf16(acc[mt][nt], aFh[mt], bFh[bi], bFh[bi + 1]);
                    }
#pragma unroll
                for (int mt = 0; mt < 2; mt++)
#pragma unroll
                    for (int nt = 0; nt < 4; nt++) {
                        int bi = (nt >> 1) * 4 + (nt & 1) * 2;
                        mma_bf16(acc[mt][nt], aFl[mt], bFh[bi], bFh[bi + 1]);
                    }
#pragma unroll
                for (int mt = 0; mt < 2; mt++)
#pragma unroll
                    for (int nt = 0; nt < 4; nt++) {
                        int bi = (nt >> 1) * 4 + (nt & 1) * 2;
                        mma_bf16(acc[mt][nt], aFh[mt], bFl[bi], bFl[bi + 1]);
                    }
            }
            __syncthreads();
        }

        const int rb = lane >> 2;
        const int cb = (lane & 3) * 2;
#pragma unroll
        for (int mt = 0; mt < 2; mt++)
#pragma unroll
            for (int nt = 0; nt < 4; nt++) {
                int row = m0 + wm + mt * 16 + rb;
                int col = n0 + wn + nt * 8 + cb;
                *reinterpret_cast<float2*>(&C[(size_t)row * N + col]) =
                    make_float2(acc[mt][nt][0], acc[mt][nt][1]);
                *reinterpret_cast<float2*>(&C[(size_t)(row + 8) * N + col]) =
                    make_float2(acc[mt][nt][2], acc[mt][nt][3]);
            }
    }
}

// ---------------------------------------------------------------------------
// RoPE + split to bf16 hi/lo. Q pre-scaled by 0.125 (exact).
// ---------------------------------------------------------------------------
__global__ __launch_bounds__(256) void rope_split_kernel(
    const float* __restrict__ cosT, const float* __restrict__ sinT)
{
    __shared__ float Vs[64][65];

    const int tid = threadIdx.x;
    const int bh = blockIdx.y;
    const int b = bh >> 4;
    const int h = bh & 15;
    const int l0 = blockIdx.x * 64;

#pragma unroll
    for (int it = 0; it < 8; it++) {
        int p = tid + it * 256;
        int l = p >> 5;
        int i = p & 31;
        int lg = l0 + l;
        size_t base = ((size_t)(b * LL + lg) * 3) * DD + h * 64;
        float c0 = cosT[lg * 64 + i],      s0 = sinT[lg * 64 + i];
        float c1 = cosT[lg * 64 + i + 32], s1 = sinT[lg * 64 + i + 32];
        size_t qi = ((size_t)bh * LL + lg) * 64;

        float q1 = g_qkv[base + i], q2 = g_qkv[base + i + 32];
        float qa = (q1 * c0 - q2 * s0) * 0.125f;
        float qb = (q2 * c1 + q1 * s1) * 0.125f;
        __nv_bfloat16 hh, ll;
        split1(qa, hh, ll); g_qh[qi + i] = hh;      g_ql[qi + i] = ll;
        split1(qb, hh, ll); g_qh[qi + i + 32] = hh; g_ql[qi + i + 32] = ll;

        float k1 = g_qkv[base + DD + i], k2 = g_qkv[base + DD + i + 32];
        float ka = k1 * c0 - k2 * s0;
        float kb = k2 * c1 + k1 * s1;
        split1(ka, hh, ll); g_kh[qi + i] = hh;      g_kl[qi + i] = ll;
        split1(kb, hh, ll); g_kh[qi + i + 32] = hh; g_kl[qi + i + 32] = ll;
    }

#pragma unroll
    for (int it = 0; it < 4; it++) {
        int f = tid + it * 256;
        int r = f >> 4;
        int dq = (f & 15) * 4;
        float4 vv = *reinterpret_cast<const float4*>(
            &g_qkv[((size_t)(b * LL + l0 + r) * 3 + 2) * DD + h * 64 + dq]);
        Vs[r][dq] = vv.x; Vs[r][dq + 1] = vv.y; Vs[r][dq + 2] = vv.z; Vs[r][dq + 3] = vv.w;
    }
    __syncthreads();
#pragma unroll
    for (int it = 0; it < 4; it++) {
        int f = tid + it * 256;
        int d = f >> 4;
        int lq = (f & 15) * 4;
        size_t vi = ((size_t)(bh * 64 + d)) * LL + l0 + lq;
        __nv_bfloat162 h2a, h2b, l2a, l2b;
        split1(Vs[lq][d],     h2a.x, l2a.x); split1(Vs[lq + 1][d], h2a.y, l2a.y);
        split1(Vs[lq + 2][d], h2b.x, l2b.x); split1(Vs[lq + 3][d], h2b.y, l2b.y);
        *reinterpret_cast<__nv_bfloat162*>(&g_vth[vi])     = h2a;
        *reinterpret_cast<__nv_bfloat162*>(&g_vth[vi + 2]) = h2b;
        *reinterpret_cast<__nv_bfloat162*>(&g_vtl[vi])     = l2a;
        *reinterpret_cast<__nv_bfloat162*>(&g_vtl[vi + 2]) = l2b;
    }
}

// ---------------------------------------------------------------------------
// Flash attention with mma.sync bf16x3 — persistent CTAs over 512 tiles.
// ---------------------------------------------------------------------------
#define FROWB 144
#define F_QTILE (128 * FROWB)             // 18432
#define F_KTILE (64 * FROWB)              // 9216
#define F_QH 0
#define F_QL F_QTILE
#define F_KV (2 * F_QTILE)                // 36864
#define F_KVSTRIDE (4 * F_KTILE)          // 36864 per buffer
#define FLASH_SMEM (F_KV + 2 * F_KVSTRIDE)  // 110592

__global__ __launch_bounds__(256, 2) void flash_mma_kernel()
{
    extern __shared__ uint8_t sm8[];
    const uint32_t sbase = smem_u32(sm8);

    const int tid  = threadIdx.x;
    const int wid  = tid >> 5;
    const int lane = tid & 31;
    const int wm = wid * 16;

    const uint32_t aOff = (uint32_t)((wm + (lane & 15)) * FROWB + (lane >> 4) * 16);
    const uint32_t bOff = (uint32_t)(((lane & 7) + ((lane >> 4) << 3)) * FROWB
                                     + ((lane >> 3) & 1) * 16);
    const int NTILES = (LL / 128) * BB * HH;   // 512

    for (int tile = blockIdx.x; tile < NTILES; tile += gridDim.x) {
        const int bh = tile >> 4;
        const int b = bh >> 4;
        const int h = bh & 15;
        const int q0 = (tile & 15) * 128;

        const __nv_bfloat16* qhp = g_qh + (size_t)bh * LL * 64;
        const __nv_bfloat16* qlp = g_ql + (size_t)bh * LL * 64;
        const __nv_bfloat16* khp = g_kh + (size_t)bh * LL * 64;
        const __nv_bfloat16* klp = g_kl + (size_t)bh * LL * 64;
        const __nv_bfloat16* vhp = g_vth + (size_t)bh * 64 * LL;
        const __nv_bfloat16* vlp = g_vtl + (size_t)bh * 64 * LL;

        // ---- prologue: Q tiles ----
        {
#pragma unroll
            for (int it = 0; it < 8; it++) {
                int op = tid + it * 256;
                int t = op >> 10;            // 0=Qh 1=Ql
                int r = (op >> 3) & 127;
                int p = op & 7;
                const __nv_bfloat16* srcp = (t == 0 ? qhp : qlp) + (size_t)(q0 + r) * 64 + p * 8;
                CP_ASYNC16(sbase + t * F_QTILE + r * FROWB + p * 16, srcp);
            }
            CP_COMMIT();
        }

        auto issue_kv = [&](int c, int buf) {
            const int kt0 = c * 64;
            const uint32_t dstb = sbase + F_KV + buf * F_KVSTRIDE;
#pragma unroll
            for (int it = 0; it < 8; it++) {
                int op = tid + it * 256;
                int t = op >> 9;             // 0=Kh 1=Kl 2=Vh 3=Vl
                int r = (op >> 3) & 63;
                int p = op & 7;
                const __nv_bfloat16* srcp;
                if (t == 0)      srcp = khp + (size_t)(kt0 + r) * 64 + p * 8;
                else if (t == 1) srcp = klp + (size_t)(kt0 + r) * 64 + p * 8;
                else if (t == 2) srcp = vhp + (size_t)r * LL + kt0 + p * 8;
                else             srcp = vlp + (size_t)r * LL + kt0 + p * 8;
                CP_ASYNC16(dstb + t * F_KTILE + r * FROWB + p * 16, srcp);
            }
            CP_COMMIT();
        };

        issue_kv(0, 0);

        uint32_t qfh[4][4], qfl[4][4];
        float o[8][4];
        float m_lo = -INFINITY, m_hi = -INFINITY, l_lo = 0.f, l_hi = 0.f;
#pragma unroll
        for (int i = 0; i < 8; i++)
#pragma unroll
            for (int j = 0; j < 4; j++) o[i][j] = 0.f;

        const int NCHUNK = LL / 64;
        for (int c = 0; c < NCHUNK; c++) {
            if (c + 1 < NCHUNK) { issue_kv(c + 1, (c + 1) & 1); CP_WAIT1(); }
            else                { CP_WAIT0(); }
            __syncthreads();

            if (c == 0) {
#pragma unroll
                for (int st = 0; st < 4; st++) {
                    ldsm_x4(qfh[st], sbase + F_QH + aOff + st * 32);
                    ldsm_x4(qfl[st], sbase + F_QL + aOff + st * 32);
                }
            }

            const uint32_t kvb = sbase + F_KV + (c & 1) * F_KVSTRIDE;
            const uint32_t khB = kvb;
            const uint32_t klB = kvb + F_KTILE;
            const uint32_t vhB = kvb + 2 * F_KTILE;
            const uint32_t vlB = kvb + 3 * F_KTILE;

            // ---- S = Q K^T (3-pass, independent-acc groups) ----
            float sa[8][4];
#pragma unroll
            for (int i = 0; i < 8; i++)
#pragma unroll
                for (int j = 0; j < 4; j++) sa[i][j] = 0.f;

#pragma unroll
            for (int st = 0; st < 4; st++) {
#pragma unroll
                for (int half = 0; half < 2; half++) {
                    uint32_t kh4[2][4], kl4[2][4];
#pragma unroll
                    for (int j = 0; j < 2; j++) {
                        int nt2 = half * 2 + j;
                        ldsm_x4(kh4[j], khB + bOff + nt2 * 16 * FROWB + st * 32);
                        ldsm_x4(kl4[j], klB + bOff + nt2 * 16 * FROWB + st * 32);
                    }
#pragma unroll
                    for (int j = 0; j < 2; j++)
#pragma unroll
                        for (int hf = 0; hf < 2; hf++) {
                            int nt = (half * 2 + j) * 2 + hf;
                            mma_bf16(sa[nt], qfh[st], kh4[j][hf * 2], kh4[j][hf * 2 + 1]);
                        }
#pragma unroll
                    for (int j = 0; j < 2; j++)
#pragma unroll
                        for (int hf = 0; hf < 2; hf++) {
                            int nt = (half * 2 + j) * 2 + hf;
                            mma_bf16(sa[nt], qfh[st], kl4[j][hf * 2], kl4[j][hf * 2 + 1]);
                        }
#pragma unroll
                    for (int j = 0; j < 2; j++)
#pragma unroll
                        for (int hf = 0; hf < 2; hf++) {
                            int nt = (half * 2 + j) * 2 + hf;
                            mma_bf16(sa[nt], qfl[st], kh4[j][hf * 2], kh4[j][hf * 2 + 1]);
                        }
                }
            }

            // ---- online softmax ----
            float mxlo = -INFINITY, mxhi = -INFINITY;
#pragma unroll
            for (int nt = 0; nt < 8; nt++) {
                mxlo = fmaxf(mxlo, fmaxf(sa[nt][0], sa[nt][1]));
                mxhi = fmaxf(mxhi, fmaxf(sa[nt][2], sa[nt][3]));
            }
            mxlo = fmaxf(mxlo, __shfl_xor_sync(0xffffffffu, mxlo, 1));
            mxlo = fmaxf(mxlo, __shfl_xor_sync(0xffffffffu, mxlo, 2));
            mxhi = fmaxf(mxhi, __shfl_xor_sync(0xffffffffu, mxhi, 1));
            mxhi = fmaxf(mxhi, __shfl_xor_sync(0xffffffffu, mxhi, 2));

            float mnlo = fmaxf(m_lo, mxlo), mnhi = fmaxf(m_hi, mxhi);
            float faclo = __expf(m_lo - mnlo), fachi = __expf(m_hi - mnhi);
            m_lo = mnlo; m_hi = mnhi;

            float rslo = 0.f, rshi = 0.f;
#pragma unroll
            for (int nt = 0; nt < 8; nt++) {
                sa[nt][0] = __expf(sa[nt][0] - mnlo);
                sa[nt][1] = __expf(sa[nt][1] - mnlo);
                sa[nt][2] = __expf(sa[nt][2] - mnhi);
                sa[nt][3] = __expf(sa[nt][3] - mnhi);
                rslo += sa[nt][0] + sa[nt][1];
                rshi += sa[nt][2] + sa[nt][3];
            }
            l_lo = l_lo * faclo + rslo;
            l_hi = l_hi * fachi + rshi;
#pragma unroll
            for (int nt = 0; nt < 8; nt++) {
                o[nt][0] *= faclo; o[nt][1] *= faclo;
                o[nt][2] *= fachi; o[nt][3] *= fachi;
            }

            // ---- P -> bf16 hi/lo A-fragments ----
            uint32_t ph[4][4], pl[4][4];
#pragma unroll
            for (int t = 0; t < 4; t++) {
#pragma unroll
                for (int half = 0; half < 2; half++) {
                    int nt = 2 * t + half;
#pragma unroll
                    for (int rr = 0; rr < 2; rr++) {
                        float x = sa[nt][rr * 2], y = sa[nt][rr * 2 + 1];
                        uint32_t hp = pack_bf16(x, y);
                        __nv_bfloat162 hv = *reinterpret_cast<__nv_bfloat162*>(&hp);
                        uint32_t lp = pack_bf16(x - __bfloat162float(hv.x),
                                                y - __bfloat162float(hv.y));
                        ph[t][half * 2 + rr] = hp;
                        pl[t][half * 2 + rr] = lp;
                    }
                }
            }

            // ---- O += P @ V (3-pass) ----
#pragma unroll
            for (int t = 0; t < 4; t++) {
#pragma unroll
                for (int half = 0; half < 2; half++) {
                    uint32_t vh4[2][4], vl4[2][4];
#pragma unroll
                    for (int j = 0; j < 2; j++) {
                        int nt2 = half * 2 + j;
                        ldsm_x4(vh4[j], vhB + bOff + nt2 * 16 * FROWB + t * 32);
                        ldsm_x4(vl4[j], vlB + bOff + nt2 * 16 * FROWB + t * 32);
                    }
#pragma unroll
                    for (int j = 0; j < 2; j++)
#pragma unroll
                        for (int hf = 0; hf < 2; hf++) {
                            int nt = (half * 2 + j) * 2 + hf;
                            mma_bf16(o[nt], ph[t], vh4[j][hf * 2], vh4[j][hf * 2 + 1]);
                        }
#pragma unroll
                    for (int j = 0; j < 2; j++)
#pragma unroll
                        for (int hf = 0; hf < 2; hf++) {
                            int nt = (half * 2 + j) * 2 + hf;
                            mma_bf16(o[nt], ph[t], vl4[j][hf * 2], vl4[j][hf * 2 + 1]);
                        }
#pragma unroll
                    for (int j = 0; j < 2; j++)
#pragma unroll
                        for (int hf = 0; hf < 2; hf++) {
                            int nt = (half * 2 + j) * 2 + hf;
                            mma_bf16(o[nt], pl[t], vh4[j][hf * 2], vh4[j][hf * 2 + 1]);
                        }
                }
            }
            __syncthreads();
        }

        // ---- epilogue ----
        l_lo += __shfl_xor_sync(0xffffffffu, l_lo, 1);
        l_lo += __shfl_xor_sync(0xffffffffu, l_lo, 2);
        l_hi += __shfl_xor_sync(0xffffffffu, l_hi, 1);
        l_hi += __shfl_xor_sync(0xffffffffu, l_hi, 2);
        float invlo = 1.f / l_lo, invhi = 1.f / l_hi;

        const int rlo = wm + (lane >> 2);
        const int cb = (lane & 3) * 2;
#pragma unroll
        for (int nt = 0; nt < 8; nt++) {
            {
                size_t idx = ((size_t)(b * LL + q0 + rlo)) * DD + h * 64 + nt * 8 + cb;
                float x = o[nt][0] * invlo, y = o[nt][1] * invlo;
                __nv_bfloat162 hv, lv;
                split1(x, hv.x, lv.x); split1(y, hv.y, lv.y);
                *reinterpret_cast<__nv_bfloat162*>(&g_ah[idx]) = hv;
                *reinterpret_cast<__nv_bfloat162*>(&g_al[idx]) = lv;
            }
            {
                size_t idx = ((size_t)(b * LL + q0 + rlo + 8)) * DD + h * 64 + nt * 8 + cb;
                float x = o[nt][2] * invhi, y = o[nt][3] * invhi;
                __nv_bfloat162 hv, lv;
                split1(x, hv.x, lv.x); split1(y, hv.y, lv.y);
                *reinterpret_cast<__nv_bfloat162*>(&g_ah[idx]) = hv;
                *reinterpret_cast<__nv_bfloat162*>(&g_al[idx]) = lv;
            }
        }
    }
}

// ---------------------------------------------------------------------------
extern "C" void kernel_launch(void* const* d_in, const int* in_sizes, int n_in,
                              void* d_out, int out_size)
{
    const float* x     = (const float*)d_in[0];
    const float* cosT  = (const float*)d_in[1];
    const float* sinT  = (const float*)d_in[2];
    const float* w_qkv = (const float*)d_in[3];
    const float* w_o   = (const float*)d_in[4];
    float* out = (float*)d_out;

    float* qkv_ptr;
    __nv_bfloat16 *xh, *xl, *wqh, *wql, *woh, *wol, *ah, *al;
    cudaGetSymbolAddress((void**)&qkv_ptr, g_qkv);
    cudaGetSymbolAddress((void**)&xh, g_xh);   cudaGetSymbolAddress((void**)&xl, g_xl);
    cudaGetSymbolAddress((void**)&wqh, g_wqh); cudaGetSymbolAddress((void**)&wql, g_wql);
    cudaGetSymbolAddress((void**)&woh, g_woh); cudaGetSymbolAddress((void**)&wol, g_wol);
    cudaGetSymbolAddress((void**)&ah, g_ah);   cudaGetSymbolAddress((void**)&al, g_al);

    cudaFuncSetAttribute(gemm_mma_kernel,
                         cudaFuncAttributeMaxDynamicSharedMemorySize, GEMM_SMEM_DYN);
    cudaFuncSetAttribute(flash_mma_kernel,
                         cudaFuncAttributeMaxDynamicSharedMemorySize, FLASH_SMEM);

    // 0. bf16 splits of x, w_qkv, w_o
    split_kernel<<<(ML * DD / 4 + 255) / 256, 256>>>(x, xh, xl, ML * DD / 4);
    split_kernel<<<(3 * DD * DD / 4 + 255) / 256, 256>>>(w_qkv, wqh, wql, 3 * DD * DD / 4);
    split_kernel<<<(DD * DD / 4 + 255) / 256, 256>>>(w_o, woh, wol, DD * DD / 4);

    // 1. QKV projection (persistent): [4096,1024] @ [3072,1024]^T
    gemm_mma_kernel<<<NPERS, 512, GEMM_SMEM_DYN>>>(xh, xl, wqh, wql, qkv_ptr,
                                                   ML, 3 * DD, DD);
    // 2. RoPE + bf16 split (q scaled by 1/8) + V transpose
    {
        dim3 grid(LL / 64, BB * HH);
        rope_split_kernel<<<grid, 256>>>(cosT, sinT);
    }
    // 3. Flash attention (persistent, mma.sync bf16x3)
    flash_mma_kernel<<<NPERS, 256, FLASH_SMEM>>>();
    // 4. Output projection (persistent): [4096,1024] @ [1024,1024]^T
    gemm_mma_kernel<<<NPERS, 512, GEMM_SMEM_DYN>>>(ah, al, woh, wol, out,
                                                   ML, DD, DD);
}

// round 13
// speedup vs baseline: 1.0335x; 1.0335x over previous
#include <cuda_runtime.h>
#include <cuda_bf16.h>
#include <math.h>
#include <cstdint>

#define BB 2
#define LL 2048
#define DD 1024
#define HH 16
#define DH 64
#define ML (BB*LL)          // 4096 rows

// ---------------------------------------------------------------------------
// Scratch (allocation-free rule: device globals)
// ---------------------------------------------------------------------------
__device__ float g_qkv[ML * 3 * DD];        // [b,l,3,h,dh] fp32 (QKV gemm out)

// bf16 flash operands (written by rope kernel)
__device__ __nv_bfloat16 g_qh[BB*HH*LL*DH], g_ql[BB*HH*LL*DH];   // [bh][l][d], pre-scaled 1/8
__device__ __nv_bfloat16 g_kh[BB*HH*LL*DH], g_kl[BB*HH*LL*DH];   // [bh][l][d]
__device__ __nv_bfloat16 g_vth[BB*HH*DH*LL], g_vtl[BB*HH*DH*LL]; // [bh][d][l]

// bf16 split operands for mma GEMMs
__device__ __nv_bfloat16 g_xh[ML * DD],      g_xl[ML * DD];
__device__ __nv_bfloat16 g_wqh[3 * DD * DD], g_wql[3 * DD * DD];
__device__ __nv_bfloat16 g_woh[DD * DD],     g_wol[DD * DD];
__device__ __nv_bfloat16 g_ah[ML * DD],      g_al[ML * DD];      // flash out hi/lo

// ---------------------------------------------------------------------------
// PTX helpers (sm_100-safe)
// ---------------------------------------------------------------------------
__device__ __forceinline__ uint32_t smem_u32(const void* p) {
    uint32_t a;
    asm("{ .reg .u64 t; cvta.to.shared.u64 t, %1; cvt.u32.u64 %0, t; }" : "=r"(a) : "l"(p));
    return a;
}
#define CP_ASYNC16(dst, src) \
    asm volatile("cp.async.cg.shared.global [%0], [%1], 16;" :: "r"(dst), "l"(src))
#define CP_COMMIT()  asm volatile("cp.async.commit_group;")
#define CP_WAIT0()   asm volatile("cp.async.wait_group 0;" ::: "memory")

__device__ __forceinline__ void ldsm_x4(uint32_t* r, uint32_t addr) {
    asm volatile("ldmatrix.sync.aligned.m8n8.x4.shared.b16 {%0,%1,%2,%3}, [%4];"
                 : "=r"(r[0]), "=r"(r[1]), "=r"(r[2]), "=r"(r[3]) : "r"(addr));
}
__device__ __forceinline__ void mma_bf16(float* d, const uint32_t* a,
                                         uint32_t b0, uint32_t b1) {
    asm volatile(
        "mma.sync.aligned.m16n8k16.row.col.f32.bf16.bf16.f32 "
        "{%0,%1,%2,%3}, {%4,%5,%6,%7}, {%8,%9}, {%0,%1,%2,%3};"
        : "+f"(d[0]), "+f"(d[1]), "+f"(d[2]), "+f"(d[3])
        : "r"(a[0]), "r"(a[1]), "r"(a[2]), "r"(a[3]), "r"(b0), "r"(b1));
}

__device__ __forceinline__ void split1(float x, __nv_bfloat16& h, __nv_bfloat16& l) {
    h = __float2bfloat16_rn(x);
    l = __float2bfloat16_rn(x - __bfloat162float(h));
}
__device__ __forceinline__ uint32_t pack_bf16(float x, float y) {
    __nv_bfloat162 t;
    t.x = __float2bfloat16_rn(x);
    t.y = __float2bfloat16_rn(y);
    return *reinterpret_cast<uint32_t*>(&t);
}

// ---------------------------------------------------------------------------
// Split fp32 -> bf16 hi/lo
// ---------------------------------------------------------------------------
__global__ __launch_bounds__(256) void split_kernel(
    const float* __restrict__ src, __nv_bfloat16* __restrict__ hi,
    __nv_bfloat16* __restrict__ lo, int n4)
{
    int i = blockIdx.x * blockDim.x + threadIdx.x;
    if (i >= n4) return;
    float4 v = reinterpret_cast<const float4*>(src)[i];
    __nv_bfloat162 hh0, hh1, ll0, ll1;
    split1(v.x, hh0.x, ll0.x); split1(v.y, hh0.y, ll0.y);
    split1(v.z, hh1.x, ll1.x); split1(v.w, hh1.y, ll1.y);
    reinterpret_cast<__nv_bfloat162*>(hi)[i * 2]     = hh0;
    reinterpret_cast<__nv_bfloat162*>(hi)[i * 2 + 1] = hh1;
    reinterpret_cast<__nv_bfloat162*>(lo)[i * 2]     = ll0;
    reinterpret_cast<__nv_bfloat162*>(lo)[i * 2 + 1] = ll1;
}

// ---------------------------------------------------------------------------
// mma.sync GEMM: C[M,N] = A[M,K] @ W[N,K]^T via bf16x3.
// 512 threads, 16 warps 4x4, 128x128 tile, K-chunk 32.
// Single-barrier pipeline: WAIT0 -> sync -> issue(c+1) -> compute(c).
// ---------------------------------------------------------------------------
#define KC 32
#define ROWB 80
#define TILE_B (128 * ROWB)
#define BUF_B  (4 * TILE_B)
#define GEMM_SMEM_DYN (2 * BUF_B)

__global__ __launch_bounds__(512, 2) void gemm_mma_kernel(
    const __nv_bfloat16* __restrict__ Ah, const __nv_bfloat16* __restrict__ Al,
    const __nv_bfloat16* __restrict__ Wh, const __nv_bfloat16* __restrict__ Wl,
    float* __restrict__ C, int M, int N, int K)
{
    extern __shared__ uint8_t sm8[];
    const uint32_t sbase = smem_u32(sm8);

    const int tid  = threadIdx.x;
    const int wid  = tid >> 5;
    const int lane = tid & 31;
    const int m0 = blockIdx.y * 128;
    const int n0 = blockIdx.x * 128;
    const int wm = (wid & 3) * 32;
    const int wn = (wid >> 2) * 32;

    float acc[2][4][4];
#pragma unroll
    for (int i = 0; i < 2; i++)
#pragma unroll
        for (int j = 0; j < 4; j++)
#pragma unroll
            for (int q = 0; q < 4; q++) acc[i][j][q] = 0.f;

    const uint32_t aOff = (uint32_t)((wm + (lane & 15)) * ROWB + (lane >> 4) * 16);
    const uint32_t bOff = (uint32_t)((wn + (lane & 7) + ((lane >> 4) << 3)) * ROWB
                                     + ((lane >> 3) & 1) * 16);
    const int nc = K / KC;

    auto issue_loads = [&](int c, int buf) {
        const int kc = c * KC;
        const uint32_t dstb = sbase + buf * BUF_B;
#pragma unroll
        for (int it = 0; it < 4; it++) {
            int op = tid + it * 512;
            int t = op >> 9;
            int r = (op >> 2) & 127;
            int p = op & 3;
            const __nv_bfloat16* srcp;
            if (t == 0)      srcp = Ah + (size_t)(m0 + r) * K + kc + p * 8;
            else if (t == 1) srcp = Al + (size_t)(m0 + r) * K + kc + p * 8;
            else if (t == 2) srcp = Wh + (size_t)(n0 + r) * K + kc + p * 8;
            else             srcp = Wl + (size_t)(n0 + r) * K + kc + p * 8;
            CP_ASYNC16(dstb + t * TILE_B + r * ROWB + p * 16, srcp);
        }
        CP_COMMIT();
    };

    issue_loads(0, 0);

    for (int c = 0; c < nc; c++) {
        CP_WAIT0();                 // outstanding = this chunk's group only
        __syncthreads();            // all warps done reading buf (c+1)&1 (chunk c-1)
        if (c + 1 < nc) issue_loads(c + 1, (c + 1) & 1);

        const uint32_t dstb = sbase + (c & 1) * BUF_B;
#pragma unroll
        for (int step = 0; step < 2; step++) {
            uint32_t aFh[2][4], aFl[2][4];
#pragma unroll
            for (int mt = 0; mt < 2; mt++) {
                ldsm_x4(aFh[mt], dstb + aOff + mt * 16 * ROWB + step * 32);
                ldsm_x4(aFl[mt], dstb + TILE_B + aOff + mt * 16 * ROWB + step * 32);
            }
            uint32_t bFh[8], bFl[8];
#pragma unroll
            for (int nt2 = 0; nt2 < 2; nt2++) {
                ldsm_x4(bFh + nt2 * 4, dstb + 2 * TILE_B + bOff + nt2 * 16 * ROWB + step * 32);
                ldsm_x4(bFl + nt2 * 4, dstb + 3 * TILE_B + bOff + nt2 * 16 * ROWB + step * 32);
            }
#pragma unroll
            for (int mt = 0; mt < 2; mt++)
#pragma unroll
                for (int nt = 0; nt < 4; nt++) {
                    int bi = (nt >> 1) * 4 + (nt & 1) * 2;
                    mma_bf16(acc[mt][nt], aFh[mt], bFh[bi], bFh[bi + 1]);
                }
#pragma unroll
            for (int mt = 0; mt < 2; mt++)
#pragma unroll
                for (int nt = 0; nt < 4; nt++) {
                    int bi = (nt >> 1) * 4 + (nt & 1) * 2;
                    mma_bf16(acc[mt][nt], aFl[mt], bFh[bi], bFh[bi + 1]);
                }
#pragma unroll
            for (int mt = 0; mt < 2; mt++)
#pragma unroll
                for (int nt = 0; nt < 4; nt++) {
                    int bi = (nt >> 1) * 4 + (nt & 1) * 2;
                    mma_bf16(acc[mt][nt], aFh[mt], bFl[bi], bFl[bi + 1]);
                }
        }
    }

    const int rb = lane >> 2;
    const int cb = (lane & 3) * 2;
#pragma unroll
    for (int mt = 0; mt < 2; mt++)
#pragma unroll
        for (int nt = 0; nt < 4; nt++) {
            int row = m0 + wm + mt * 16 + rb;
            int col = n0 + wn + nt * 8 + cb;
            *reinterpret_cast<float2*>(&C[(size_t)row * N + col]) =
                make_float2(acc[mt][nt][0], acc[mt][nt][1]);
            *reinterpret_cast<float2*>(&C[(size_t)(row + 8) * N + col]) =
                make_float2(acc[mt][nt][2], acc[mt][nt][3]);
        }
}

// ---------------------------------------------------------------------------
// RoPE + split to bf16 hi/lo. Q pre-scaled by 0.125 (exact).
// ---------------------------------------------------------------------------
__global__ __launch_bounds__(256) void rope_split_kernel(
    const float* __restrict__ cosT, const float* __restrict__ sinT)
{
    __shared__ float Vs[64][65];

    const int tid = threadIdx.x;
    const int bh = blockIdx.y;
    const int b = bh >> 4;
    const int h = bh & 15;
    const int l0 = blockIdx.x * 64;

#pragma unroll
    for (int it = 0; it < 8; it++) {
        int p = tid + it * 256;
        int l = p >> 5;
        int i = p & 31;
        int lg = l0 + l;
        size_t base = ((size_t)(b * LL + lg) * 3) * DD + h * 64;
        float c0 = cosT[lg * 64 + i],      s0 = sinT[lg * 64 + i];
        float c1 = cosT[lg * 64 + i + 32], s1 = sinT[lg * 64 + i + 32];
        size_t qi = ((size_t)bh * LL + lg) * 64;

        float q1 = g_qkv[base + i], q2 = g_qkv[base + i + 32];
        float qa = (q1 * c0 - q2 * s0) * 0.125f;
        float qb = (q2 * c1 + q1 * s1) * 0.125f;
        __nv_bfloat16 hh, ll;
        split1(qa, hh, ll); g_qh[qi + i] = hh;      g_ql[qi + i] = ll;
        split1(qb, hh, ll); g_qh[qi + i + 32] = hh; g_ql[qi + i + 32] = ll;

        float k1 = g_qkv[base + DD + i], k2 = g_qkv[base + DD + i + 32];
        float ka = k1 * c0 - k2 * s0;
        float kb = k2 * c1 + k1 * s1;
        split1(ka, hh, ll); g_kh[qi + i] = hh;      g_kl[qi + i] = ll;
        split1(kb, hh, ll); g_kh[qi + i + 32] = hh; g_kl[qi + i + 32] = ll;
    }

#pragma unroll
    for (int it = 0; it < 4; it++) {
        int f = tid + it * 256;
        int r = f >> 4;
        int dq = (f & 15) * 4;
        float4 vv = *reinterpret_cast<const float4*>(
            &g_qkv[((size_t)(b * LL + l0 + r) * 3 + 2) * DD + h * 64 + dq]);
        Vs[r][dq] = vv.x; Vs[r][dq + 1] = vv.y; Vs[r][dq + 2] = vv.z; Vs[r][dq + 3] = vv.w;
    }
    __syncthreads();
#pragma unroll
    for (int it = 0; it < 4; it++) {
        int f = tid + it * 256;
        int d = f >> 4;
        int lq = (f & 15) * 4;
        size_t vi = ((size_t)(bh * 64 + d)) * LL + l0 + lq;
        __nv_bfloat162 h2a, h2b, l2a, l2b;
        split1(Vs[lq][d],     h2a.x, l2a.x); split1(Vs[lq + 1][d], h2a.y, l2a.y);
        split1(Vs[lq + 2][d], h2b.x, l2b.x); split1(Vs[lq + 3][d], h2b.y, l2b.y);
        *reinterpret_cast<__nv_bfloat162*>(&g_vth[vi])     = h2a;
        *reinterpret_cast<__nv_bfloat162*>(&g_vth[vi + 2]) = h2b;
        *reinterpret_cast<__nv_bfloat162*>(&g_vtl[vi])     = l2a;
        *reinterpret_cast<__nv_bfloat162*>(&g_vtl[vi + 2]) = l2b;
    }
}

// ---------------------------------------------------------------------------
// Flash attention with mma.sync bf16x3, single-barrier pipeline.
// ---------------------------------------------------------------------------
#define FROWB 144
#define F_QTILE (128 * FROWB)             // 18432
#define F_KTILE (64 * FROWB)              // 9216
#define F_QH 0
#define F_QL F_QTILE
#define F_KV (2 * F_QTILE)                // 36864
#define F_KVSTRIDE (4 * F_KTILE)          // 36864 per buffer
#define FLASH_SMEM (F_KV + 2 * F_KVSTRIDE)  // 110592

__global__ __launch_bounds__(256, 2) void flash_mma_kernel()
{
    extern __shared__ uint8_t sm8[];
    const uint32_t sbase = smem_u32(sm8);

    const int tid  = threadIdx.x;
    const int wid  = tid >> 5;
    const int lane = tid & 31;
    const int bh = blockIdx.y;
    const int b = bh >> 4;
    const int h = bh & 15;
    const int q0 = blockIdx.x * 128;
    const int wm = wid * 16;

    const __nv_bfloat16* qhp = g_qh + (size_t)bh * LL * 64;
    const __nv_bfloat16* qlp = g_ql + (size_t)bh * LL * 64;
    const __nv_bfloat16* khp = g_kh + (size_t)bh * LL * 64;
    const __nv_bfloat16* klp = g_kl + (size_t)bh * LL * 64;
    const __nv_bfloat16* vhp = g_vth + (size_t)bh * 64 * LL;
    const __nv_bfloat16* vlp = g_vtl + (size_t)bh * 64 * LL;

    const uint32_t aOff = (uint32_t)((wm + (lane & 15)) * FROWB + (lane >> 4) * 16);
    const uint32_t bOff = (uint32_t)(((lane & 7) + ((lane >> 4) << 3)) * FROWB
                                     + ((lane >> 3) & 1) * 16);

    // ---- prologue: Q tiles ----
    {
#pragma unroll
        for (int it = 0; it < 8; it++) {
            int op = tid + it * 256;
            int t = op >> 10;            // 0=Qh 1=Ql
            int r = (op >> 3) & 127;
            int p = op & 7;
            const __nv_bfloat16* srcp = (t == 0 ? qhp : qlp) + (size_t)(q0 + r) * 64 + p * 8;
            CP_ASYNC16(sbase + t * F_QTILE + r * FROWB + p * 16, srcp);
        }
        CP_COMMIT();
    }

    auto issue_kv = [&](int c, int buf) {
        const int kt0 = c * 64;
        const uint32_t dstb = sbase + F_KV + buf * F_KVSTRIDE;
#pragma unroll
        for (int it = 0; it < 8; it++) {
            int op = tid + it * 256;
            int t = op >> 9;             // 0=Kh 1=Kl 2=Vh 3=Vl
            int r = (op >> 3) & 63;
            int p = op & 7;
            const __nv_bfloat16* srcp;
            if (t == 0)      srcp = khp + (size_t)(kt0 + r) * 64 + p * 8;
            else if (t == 1) srcp = klp + (size_t)(kt0 + r) * 64 + p * 8;
            else if (t == 2) srcp = vhp + (size_t)r * LL + kt0 + p * 8;
            else             srcp = vlp + (size_t)r * LL + kt0 + p * 8;
            CP_ASYNC16(dstb + t * F_KTILE + r * FROWB + p * 16, srcp);
        }
        CP_COMMIT();
    };

    issue_kv(0, 0);

    uint32_t qfh[4][4], qfl[4][4];
    float o[8][4];
    float m_lo = -INFINITY, m_hi = -INFINITY, l_lo = 0.f, l_hi = 0.f;
#pragma unroll
    for (int i = 0; i < 8; i++)
#pragma unroll
        for (int j = 0; j < 4; j++) o[i][j] = 0.f;

    const int NCHUNK = LL / 64;
    for (int c = 0; c < NCHUNK; c++) {
        CP_WAIT0();                 // waits Q (at c=0) + kv chunk c
        __syncthreads();            // all warps done reading buf (c+1)&1
        if (c + 1 < NCHUNK) issue_kv(c + 1, (c + 1) & 1);

        if (c == 0) {
#pragma unroll
            for (int st = 0; st < 4; st++) {
                ldsm_x4(qfh[st], sbase + F_QH + aOff + st * 32);
                ldsm_x4(qfl[st], sbase + F_QL + aOff + st * 32);
            }
        }

        const uint32_t kvb = sbase + F_KV + (c & 1) * F_KVSTRIDE;
        const uint32_t khB = kvb;
        const uint32_t klB = kvb + F_KTILE;
        const uint32_t vhB = kvb + 2 * F_KTILE;
        const uint32_t vlB = kvb + 3 * F_KTILE;

        // ---- S = Q K^T (3-pass, independent-acc groups) ----
        float sa[8][4];
#pragma unroll
        for (int i = 0; i < 8; i++)
#pragma unroll
            for (int j = 0; j < 4; j++) sa[i][j] = 0.f;

#pragma unroll
        for (int st = 0; st < 4; st++) {
#pragma unroll
            for (int half = 0; half < 2; half++) {
                uint32_t kh4[2][4], kl4[2][4];
#pragma unroll
                for (int j = 0; j < 2; j++) {
                    int nt2 = half * 2 + j;
                    ldsm_x4(kh4[j], khB + bOff + nt2 * 16 * FROWB + st * 32);
                    ldsm_x4(kl4[j], klB + bOff + nt2 * 16 * FROWB + st * 32);
                }
#pragma unroll
                for (int j = 0; j < 2; j++)
#pragma unroll
                    for (int hf = 0; hf < 2; hf++) {
                        int nt = (half * 2 + j) * 2 + hf;
                        mma_bf16(sa[nt], qfh[st], kh4[j][hf * 2], kh4[j][hf * 2 + 1]);
                    }
#pragma unroll
                for (int j = 0; j < 2; j++)
#pragma unroll
                    for (int hf = 0; hf < 2; hf++) {
                        int nt = (half * 2 + j) * 2 + hf;
                        mma_bf16(sa[nt], qfh[st], kl4[j][hf * 2], kl4[j][hf * 2 + 1]);
                    }
#pragma unroll
                for (int j = 0; j < 2; j++)
#pragma unroll
                    for (int hf = 0; hf < 2; hf++) {
                        int nt = (half * 2 + j) * 2 + hf;
                        mma_bf16(sa[nt], qfl[st], kh4[j][hf * 2], kh4[j][hf * 2 + 1]);
                    }
            }
        }

        // ---- online softmax (rows lo: lane/4, hi: +8) ----
        float mxlo = -INFINITY, mxhi = -INFINITY;
#pragma unroll
        for (int nt = 0; nt < 8; nt++) {
            mxlo = fmaxf(mxlo, fmaxf(sa[nt][0], sa[nt][1]));
            mxhi = fmaxf(mxhi, fmaxf(sa[nt][2], sa[nt][3]));
        }
        mxlo = fmaxf(mxlo, __shfl_xor_sync(0xffffffffu, mxlo, 1));
        mxlo = fmaxf(mxlo, __shfl_xor_sync(0xffffffffu, mxlo, 2));
        mxhi = fmaxf(mxhi, __shfl_xor_sync(0xffffffffu, mxhi, 1));
        mxhi = fmaxf(mxhi, __shfl_xor_sync(0xffffffffu, mxhi, 2));

        float mnlo = fmaxf(m_lo, mxlo), mnhi = fmaxf(m_hi, mxhi);
        float faclo = __expf(m_lo - mnlo), fachi = __expf(m_hi - mnhi);
        m_lo = mnlo; m_hi = mnhi;

        float rslo = 0.f, rshi = 0.f;
#pragma unroll
        for (int nt = 0; nt < 8; nt++) {
            sa[nt][0] = __expf(sa[nt][0] - mnlo);
            sa[nt][1] = __expf(sa[nt][1] - mnlo);
            sa[nt][2] = __expf(sa[nt][2] - mnhi);
            sa[nt][3] = __expf(sa[nt][3] - mnhi);
            rslo += sa[nt][0] + sa[nt][1];
            rshi += sa[nt][2] + sa[nt][3];
        }
        l_lo = l_lo * faclo + rslo;
        l_hi = l_hi * fachi + rshi;
#pragma unroll
        for (int nt = 0; nt < 8; nt++) {
            o[nt][0] *= faclo; o[nt][1] *= faclo;
            o[nt][2] *= fachi; o[nt][3] *= fachi;
        }

        // ---- P -> bf16 hi/lo A-fragments ----
        uint32_t ph[4][4], pl[4][4];
#pragma unroll
        for (int t = 0; t < 4; t++) {
#pragma unroll
            for (int half = 0; half < 2; half++) {
                int nt = 2 * t + half;
#pragma unroll
                for (int rr = 0; rr < 2; rr++) {
                    float x = sa[nt][rr * 2], y = sa[nt][rr * 2 + 1];
                    uint32_t hp = pack_bf16(x, y);
                    __nv_bfloat162 hv = *reinterpret_cast<__nv_bfloat162*>(&hp);
                    uint32_t lp = pack_bf16(x - __bfloat162float(hv.x),
                                            y - __bfloat162float(hv.y));
                    ph[t][half * 2 + rr] = hp;
                    pl[t][half * 2 + rr] = lp;
                }
            }
        }

        // ---- O += P @ V (3-pass, independent-acc groups) ----
#pragma unroll
        for (int t = 0; t < 4; t++) {
#pragma unroll
            for (int half = 0; half < 2; half++) {
                uint32_t vh4[2][4], vl4[2][4];
#pragma unroll
                for (int j = 0; j < 2; j++) {
                    int nt2 = half * 2 + j;
                    ldsm_x4(vh4[j], vhB + bOff + nt2 * 16 * FROWB + t * 32);
                    ldsm_x4(vl4[j], vlB + bOff + nt2 * 16 * FROWB + t * 32);
                }
#pragma unroll
                for (int j = 0; j < 2; j++)
#pragma unroll
                    for (int hf = 0; hf < 2; hf++) {
                        int nt = (half * 2 + j) * 2 + hf;
                        mma_bf16(o[nt], ph[t], vh4[j][hf * 2], vh4[j][hf * 2 + 1]);
                    }
#pragma unroll
                for (int j = 0; j < 2; j++)
#pragma unroll
                    for (int hf = 0; hf < 2; hf++) {
                        int nt = (half * 2 + j) * 2 + hf;
                        mma_bf16(o[nt], ph[t], vl4[j][hf * 2], vl4[j][hf * 2 + 1]);
                    }
#pragma unroll
                for (int j = 0; j < 2; j++)
#pragma unroll
                    for (int hf = 0; hf < 2; hf++) {
                        int nt = (half * 2 + j) * 2 + hf;
                        mma_bf16(o[nt], pl[t], vh4[j][hf * 2], vh4[j][hf * 2 + 1]);
                    }
            }
        }
    }

    // ---- epilogue: normalize, write bf16 hi/lo to g_ah/g_al ----
    l_lo += __shfl_xor_sync(0xffffffffu, l_lo, 1);
    l_lo += __shfl_xor_sync(0xffffffffu, l_lo, 2);
    l_hi += __shfl_xor_sync(0xffffffffu, l_hi, 1);
    l_hi += __shfl_xor_sync(0xffffffffu, l_hi, 2);
    float invlo = 1.f / l_lo, invhi = 1.f / l_hi;

    const int rlo = wm + (lane >> 2);
    const int cb = (lane & 3) * 2;
#pragma unroll
    for (int nt = 0; nt < 8; nt++) {
        {
            size_t idx = ((size_t)(b * LL + q0 + rlo)) * DD + h * 64 + nt * 8 + cb;
            float x = o[nt][0] * invlo, y = o[nt][1] * invlo;
            __nv_bfloat162 hv, lv;
            split1(x, hv.x, lv.x); split1(y, hv.y, lv.y);
            *reinterpret_cast<__nv_bfloat162*>(&g_ah[idx]) = hv;
            *reinterpret_cast<__nv_bfloat162*>(&g_al[idx]) = lv;
        }
        {
            size_t idx = ((size_t)(b * LL + q0 + rlo + 8)) * DD + h * 64 + nt * 8 + cb;
            float x = o[nt][2] * invhi, y = o[nt][3] * invhi;
            __nv_bfloat162 hv, lv;
            split1(x, hv.x, lv.x); split1(y, hv.y, lv.y);
            *reinterpret_cast<__nv_bfloat162*>(&g_ah[idx]) = hv;
            *reinterpret_cast<__nv_bfloat162*>(&g_al[idx]) = lv;
        }
    }
}

// ---------------------------------------------------------------------------
extern "C" void kernel_launch(void* const* d_in, const int* in_sizes, int n_in,
                              void* d_out, int out_size)
{
    const float* x     = (const float*)d_in[0];
    const float* cosT  = (const float*)d_in[1];
    const float* sinT  = (const float*)d_in[2];
    const float* w_qkv = (const float*)d_in[3];
    const float* w_o   = (const float*)d_in[4];
    float* out = (float*)d_out;

    float* qkv_ptr;
    __nv_bfloat16 *xh, *xl, *wqh, *wql, *woh, *wol, *ah, *al;
    cudaGetSymbolAddress((void**)&qkv_ptr, g_qkv);
    cudaGetSymbolAddress((void**)&xh, g_xh);   cudaGetSymbolAddress((void**)&xl, g_xl);
    cudaGetSymbolAddress((void**)&wqh, g_wqh); cudaGetSymbolAddress((void**)&wql, g_wql);
    cudaGetSymbolAddress((void**)&woh, g_woh); cudaGetSymbolAddress((void**)&wol, g_wol);
    cudaGetSymbolAddress((void**)&ah, g_ah);   cudaGetSymbolAddress((void**)&al, g_al);

    cudaFuncSetAttribute(gemm_mma_kernel,
                         cudaFuncAttributeMaxDynamicSharedMemorySize, GEMM_SMEM_DYN);
    cudaFuncSetAttribute(flash_mma_kernel,
                         cudaFuncAttributeMaxDynamicSharedMemorySize, FLASH_SMEM);

    // 0. bf16 splits of x, w_qkv, w_o
    split_kernel<<<(ML * DD / 4 + 255) / 256, 256>>>(x, xh, xl, ML * DD / 4);
    split_kernel<<<(3 * DD * DD / 4 + 255) / 256, 256>>>(w_qkv, wqh, wql, 3 * DD * DD / 4);
    split_kernel<<<(DD * DD / 4 + 255) / 256, 256>>>(w_o, woh, wol, DD * DD / 4);

    // 1. QKV projection (mma.sync): [4096,1024] @ [3072,1024]^T
    {
        dim3 grid(3 * DD / 128, ML / 128);
        gemm_mma_kernel<<<grid, 512, GEMM_SMEM_DYN>>>(xh, xl, wqh, wql, qkv_ptr,
                                                      ML, 3 * DD, DD);
    }
    // 2. RoPE + bf16 split (q scaled by 1/8) + V transpose
    {
        dim3 grid(LL / 64, BB * HH);
        rope_split_kernel<<<grid, 256>>>(cosT, sinT);
    }
    // 3. Flash attention (mma.sync bf16x3) -> writes g_ah/g_al directly
    {
        dim3 grid(LL / 128, BB * HH);
        flash_mma_kernel<<<grid, 256, FLASH_SMEM>>>();
    }
    // 4. Output projection (mma.sync): [4096,1024] @ [1024,1024]^T
    {
        dim3 grid(DD / 128, ML / 128);
        gemm_mma_kernel<<<grid, 512, GEMM_SMEM_DYN>>>(ah, al, woh, wol, out,
                                                      ML, DD, DD);
    }
}

// round 14
// speedup vs baseline: 1.0389x; 1.0052x over previous
#include <cuda_runtime.h>
#include <cuda_bf16.h>
#include <math.h>
#include <cstdint>

#define BB 2
#define LL 2048
#define DD 1024
#define HH 16
#define DH 64
#define ML (BB*LL)          // 4096 rows
#define NPERS 296

// ---------------------------------------------------------------------------
// Scratch (allocation-free rule: device globals)
// ---------------------------------------------------------------------------
__device__ float g_qkv[ML * 3 * DD];        // [b,l,3,h,dh] fp32 (QKV gemm out)

__device__ __nv_bfloat16 g_qh[BB*HH*LL*DH], g_ql[BB*HH*LL*DH];   // [bh][l][d], pre-scaled 1/8
__device__ __nv_bfloat16 g_kh[BB*HH*LL*DH], g_kl[BB*HH*LL*DH];   // [bh][l][d]
__device__ __nv_bfloat16 g_vth[BB*HH*DH*LL], g_vtl[BB*HH*DH*LL]; // [bh][d][l]

__device__ __nv_bfloat16 g_xh[ML * DD],      g_xl[ML * DD];
__device__ __nv_bfloat16 g_wqh[3 * DD * DD], g_wql[3 * DD * DD];
__device__ __nv_bfloat16 g_woh[DD * DD],     g_wol[DD * DD];
__device__ __nv_bfloat16 g_ah[ML * DD],      g_al[ML * DD];      // flash out hi/lo

// ---------------------------------------------------------------------------
// PTX helpers (sm_100-safe)
// ---------------------------------------------------------------------------
__device__ __forceinline__ uint32_t smem_u32(const void* p) {
    uint32_t a;
    asm("{ .reg .u64 t; cvta.to.shared.u64 t, %1; cvt.u32.u64 %0, t; }" : "=r"(a) : "l"(p));
    return a;
}
#define CP_ASYNC16(dst, src) \
    asm volatile("cp.async.cg.shared.global [%0], [%1], 16;" :: "r"(dst), "l"(src))
#define CP_COMMIT()  asm volatile("cp.async.commit_group;")
#define CP_WAIT0()   asm volatile("cp.async.wait_group 0;" ::: "memory")

__device__ __forceinline__ void ldsm_x4(uint32_t* r, uint32_t addr) {
    asm volatile("ldmatrix.sync.aligned.m8n8.x4.shared.b16 {%0,%1,%2,%3}, [%4];"
                 : "=r"(r[0]), "=r"(r[1]), "=r"(r[2]), "=r"(r[3]) : "r"(addr));
}
__device__ __forceinline__ void mma_bf16(float* d, const uint32_t* a,
                                         uint32_t b0, uint32_t b1) {
    asm volatile(
        "mma.sync.aligned.m16n8k16.row.col.f32.bf16.bf16.f32 "
        "{%0,%1,%2,%3}, {%4,%5,%6,%7}, {%8,%9}, {%0,%1,%2,%3};"
        : "+f"(d[0]), "+f"(d[1]), "+f"(d[2]), "+f"(d[3])
        : "r"(a[0]), "r"(a[1]), "r"(a[2]), "r"(a[3]), "r"(b0), "r"(b1));
}

__device__ __forceinline__ void split1(float x, __nv_bfloat16& h, __nv_bfloat16& l) {
    h = __float2bfloat16_rn(x);
    l = __float2bfloat16_rn(x - __bfloat162float(h));
}
__device__ __forceinline__ uint32_t pack_bf16(float x, float y) {
    __nv_bfloat162 t;
    t.x = __float2bfloat16_rn(x);
    t.y = __float2bfloat16_rn(y);
    return *reinterpret_cast<uint32_t*>(&t);
}

// ---------------------------------------------------------------------------
// Fused split: x, w_qkv, w_o in one launch (segmented grid-stride)
// ---------------------------------------------------------------------------
#define N4_X   (ML * DD / 4)
#define N4_WQ  (3 * DD * DD / 4)
#define N4_WO  (DD * DD / 4)
#define N4_TOT (N4_X + N4_WQ + N4_WO)

__global__ __launch_bounds__(256) void fused_split_kernel(
    const float* __restrict__ x, const float* __restrict__ wq,
    const float* __restrict__ wo)
{
    int i = blockIdx.x * blockDim.x + threadIdx.x;
    if (i >= N4_TOT) return;
    const float* src;
    __nv_bfloat16 *hi, *lo;
    int idx;
    if (i < N4_X)             { src = x;  hi = g_xh;  lo = g_xl;  idx = i; }
    else if (i < N4_X + N4_WQ){ src = wq; hi = g_wqh; lo = g_wql; idx = i - N4_X; }
    else                      { src = wo; hi = g_woh; lo = g_wol; idx = i - N4_X - N4_WQ; }

    float4 v = reinterpret_cast<const float4*>(src)[idx];
    __nv_bfloat162 hh0, hh1, ll0, ll1;
    split1(v.x, hh0.x, ll0.x); split1(v.y, hh0.y, ll0.y);
    split1(v.z, hh1.x, ll1.x); split1(v.w, hh1.y, ll1.y);
    reinterpret_cast<__nv_bfloat162*>(hi)[idx * 2]     = hh0;
    reinterpret_cast<__nv_bfloat162*>(hi)[idx * 2 + 1] = hh1;
    reinterpret_cast<__nv_bfloat162*>(lo)[idx * 2]     = ll0;
    reinterpret_cast<__nv_bfloat162*>(lo)[idx * 2 + 1] = ll1;
}

// ---------------------------------------------------------------------------
// mma.sync GEMM, persistent with cross-tile chunk-0 prefetch.
// 512 threads, 16 warps 4x4, 128x128 tile, K-chunk 32.
// ---------------------------------------------------------------------------
#define KC 32
#define ROWB 80
#define TILE_B (128 * ROWB)
#define BUF_B  (4 * TILE_B)
#define GEMM_SMEM_DYN (2 * BUF_B)

__global__ __launch_bounds__(512, 2) void gemm_mma_kernel(
    const __nv_bfloat16* __restrict__ Ah, const __nv_bfloat16* __restrict__ Al,
    const __nv_bfloat16* __restrict__ Wh, const __nv_bfloat16* __restrict__ Wl,
    float* __restrict__ C, int M, int N, int K)
{
    extern __shared__ uint8_t sm8[];
    const uint32_t sbase = smem_u32(sm8);

    const int tid  = threadIdx.x;
    const int wid  = tid >> 5;
    const int lane = tid & 31;
    const int wm = (wid & 3) * 32;
    const int wn = (wid >> 2) * 32;

    const uint32_t aOff = (uint32_t)((wm + (lane & 15)) * ROWB + (lane >> 4) * 16);
    const uint32_t bOff = (uint32_t)((wn + (lane & 7) + ((lane >> 4) << 3)) * ROWB
                                     + ((lane >> 3) & 1) * 16);
    const int nc = K / KC;                 // even (32 or 32)
    const int ntn = N >> 7;
    const int ntiles = (M >> 7) * ntn;

    // issue chunk c of tile 'tile' into buffer 'buf'
    auto issue_for = [&](int tile, int c, int buf) {
        const int m0 = (tile / ntn) * 128;
        const int n0 = (tile % ntn) * 128;
        const int kc = c * KC;
        const uint32_t dstb = sbase + buf * BUF_B;
#pragma unroll
        for (int it = 0; it < 4; it++) {
            int op = tid + it * 512;
            int t = op >> 9;
            int r = (op >> 2) & 127;
            int p = op & 3;
            const __nv_bfloat16* srcp;
            if (t == 0)      srcp = Ah + (size_t)(m0 + r) * K + kc + p * 8;
            else if (t == 1) srcp = Al + (size_t)(m0 + r) * K + kc + p * 8;
            else if (t == 2) srcp = Wh + (size_t)(n0 + r) * K + kc + p * 8;
            else             srcp = Wl + (size_t)(n0 + r) * K + kc + p * 8;
            CP_ASYNC16(dstb + t * TILE_B + r * ROWB + p * 16, srcp);
        }
        CP_COMMIT();
    };

    if (blockIdx.x < (unsigned)ntiles) issue_for(blockIdx.x, 0, 0);

    for (int tile = blockIdx.x; tile < ntiles; tile += gridDim.x) {
        const int m0 = (tile / ntn) * 128;
        const int n0 = (tile % ntn) * 128;

        float acc[2][4][4];
#pragma unroll
        for (int i = 0; i < 2; i++)
#pragma unroll
            for (int j = 0; j < 4; j++)
#pragma unroll
                for (int q = 0; q < 4; q++) acc[i][j][q] = 0.f;

        for (int c = 0; c < nc; c++) {
            CP_WAIT0();
            __syncthreads();
            if (c + 1 < nc) {
                issue_for(tile, c + 1, (c + 1) & 1);
            } else if (tile + gridDim.x < ntiles) {
                issue_for(tile + gridDim.x, 0, 0);   // nc even -> buf 0 free
            }

            const uint32_t dstb = sbase + (c & 1) * BUF_B;
#pragma unroll
            for (int step = 0; step < 2; step++) {
                uint32_t aFh[2][4], aFl[2][4];
#pragma unroll
                for (int mt = 0; mt < 2; mt++) {
                    ldsm_x4(aFh[mt], dstb + aOff + mt * 16 * ROWB + step * 32);
                    ldsm_x4(aFl[mt], dstb + TILE_B + aOff + mt * 16 * ROWB + step * 32);
                }
                uint32_t bFh[8], bFl[8];
#pragma unroll
                for (int nt2 = 0; nt2 < 2; nt2++) {
                    ldsm_x4(bFh + nt2 * 4, dstb + 2 * TILE_B + bOff + nt2 * 16 * ROWB + step * 32);
                    ldsm_x4(bFl + nt2 * 4, dstb + 3 * TILE_B + bOff + nt2 * 16 * ROWB + step * 32);
                }
#pragma unroll
                for (int mt = 0; mt < 2; mt++)
#pragma unroll
                    for (int nt = 0; nt < 4; nt++) {
                        int bi = (nt >> 1) * 4 + (nt & 1) * 2;
                        mma_bf16(acc[mt][nt], aFh[mt], bFh[bi], bFh[bi + 1]);
                    }
#pragma unroll
                for (int mt = 0; mt < 2; mt++)
#pragma unroll
                    for (int nt = 0; nt < 4; nt++) {
                        int bi = (nt >> 1) * 4 + (nt & 1) * 2;
                        mma_bf16(acc[mt][nt], aFl[mt], bFh[bi], bFh[bi + 1]);
                    }
#pragma unroll
                for (int mt = 0; mt < 2; mt++)
#pragma unroll
                    for (int nt = 0; nt < 4; nt++) {
                        int bi = (nt >> 1) * 4 + (nt & 1) * 2;
                        mma_bf16(acc[mt][nt], aFh[mt], bFl[bi], bFl[bi + 1]);
                    }
            }
        }

        const int rb = lane >> 2;
        const int cb = (lane & 3) * 2;
#pragma unroll
        for (int mt = 0; mt < 2; mt++)
#pragma unroll
            for (int nt = 0; nt < 4; nt++) {
                int row = m0 + wm + mt * 16 + rb;
                int col = n0 + wn + nt * 8 + cb;
                *reinterpret_cast<float2*>(&C[(size_t)row * N + col]) =
                    make_float2(acc[mt][nt][0], acc[mt][nt][1]);
                *reinterpret_cast<float2*>(&C[(size_t)(row + 8) * N + col]) =
                    make_float2(acc[mt][nt][2], acc[mt][nt][3]);
            }
    }
}

// ---------------------------------------------------------------------------
// RoPE + split to bf16 hi/lo. Q pre-scaled by 0.125 (exact).
// ---------------------------------------------------------------------------
__global__ __launch_bounds__(256) void rope_split_kernel(
    const float* __restrict__ cosT, const float* __restrict__ sinT)
{
    __shared__ float Vs[64][65];

    const int tid = threadIdx.x;
    const int bh = blockIdx.y;
    const int b = bh >> 4;
    const int h = bh & 15;
    const int l0 = blockIdx.x * 64;

#pragma unroll
    for (int it = 0; it < 8; it++) {
        int p = tid + it * 256;
        int l = p >> 5;
        int i = p & 31;
        int lg = l0 + l;
        size_t base = ((size_t)(b * LL + lg) * 3) * DD + h * 64;
        float c0 = cosT[lg * 64 + i],      s0 = sinT[lg * 64 + i];
        float c1 = cosT[lg * 64 + i + 32], s1 = sinT[lg * 64 + i + 32];
        size_t qi = ((size_t)bh * LL + lg) * 64;

        float q1 = g_qkv[base + i], q2 = g_qkv[base + i + 32];
        float qa = (q1 * c0 - q2 * s0) * 0.125f;
        float qb = (q2 * c1 + q1 * s1) * 0.125f;
        __nv_bfloat16 hh, ll;
        split1(qa, hh, ll); g_qh[qi + i] = hh;      g_ql[qi + i] = ll;
        split1(qb, hh, ll); g_qh[qi + i + 32] = hh; g_ql[qi + i + 32] = ll;

        float k1 = g_qkv[base + DD + i], k2 = g_qkv[base + DD + i + 32];
        float ka = k1 * c0 - k2 * s0;
        float kb = k2 * c1 + k1 * s1;
        split1(ka, hh, ll); g_kh[qi + i] = hh;      g_kl[qi + i] = ll;
        split1(kb, hh, ll); g_kh[qi + i + 32] = hh; g_kl[qi + i + 32] = ll;
    }

#pragma unroll
    for (int it = 0; it < 4; it++) {
        int f = tid + it * 256;
        int r = f >> 4;
        int dq = (f & 15) * 4;
        float4 vv = *reinterpret_cast<const float4*>(
            &g_qkv[((size_t)(b * LL + l0 + r) * 3 + 2) * DD + h * 64 + dq]);
        Vs[r][dq] = vv.x; Vs[r][dq + 1] = vv.y; Vs[r][dq + 2] = vv.z; Vs[r][dq + 3] = vv.w;
    }
    __syncthreads();
#pragma unroll
    for (int it = 0; it < 4; it++) {
        int f = tid + it * 256;
        int d = f >> 4;
        int lq = (f & 15) * 4;
        size_t vi = ((size_t)(bh * 64 + d)) * LL + l0 + lq;
        __nv_bfloat162 h2a, h2b, l2a, l2b;
        split1(Vs[lq][d],     h2a.x, l2a.x); split1(Vs[lq + 1][d], h2a.y, l2a.y);
        split1(Vs[lq + 2][d], h2b.x, l2b.x); split1(Vs[lq + 3][d], h2b.y, l2b.y);
        *reinterpret_cast<__nv_bfloat162*>(&g_vth[vi])     = h2a;
        *reinterpret_cast<__nv_bfloat162*>(&g_vth[vi + 2]) = h2b;
        *reinterpret_cast<__nv_bfloat162*>(&g_vtl[vi])     = l2a;
        *reinterpret_cast<__nv_bfloat162*>(&g_vtl[vi + 2]) = l2b;
    }
}

// ---------------------------------------------------------------------------
// Flash attention, persistent with cross-tile Q + chunk-0 prefetch.
// ---------------------------------------------------------------------------
#define FROWB 144
#define F_QTILE (128 * FROWB)             // 18432
#define F_KTILE (64 * FROWB)              // 9216
#define F_QH 0
#define F_QL F_QTILE
#define F_KV (2 * F_QTILE)                // 36864
#define F_KVSTRIDE (4 * F_KTILE)          // 36864 per buffer
#define FLASH_SMEM (F_KV + 2 * F_KVSTRIDE)  // 110592
#define F_NTILES ((LL / 128) * BB * HH)   // 512
#define F_NCHUNK (LL / 64)                // 32 (even)

__global__ __launch_bounds__(256, 2) void flash_mma_kernel()
{
    extern __shared__ uint8_t sm8[];
    const uint32_t sbase = smem_u32(sm8);

    const int tid  = threadIdx.x;
    const int wid  = tid >> 5;
    const int lane = tid & 31;
    const int wm = wid * 16;

    const uint32_t aOff = (uint32_t)((wm + (lane & 15)) * FROWB + (lane >> 4) * 16);
    const uint32_t bOff = (uint32_t)(((lane & 7) + ((lane >> 4) << 3)) * FROWB
                                     + ((lane >> 3) & 1) * 16);

    auto issue_q_for = [&](int tile) {
        const int bh = tile >> 4;
        const int q0 = (tile & 15) * 128;
        const __nv_bfloat16* qhp = g_qh + (size_t)bh * LL * 64;
        const __nv_bfloat16* qlp = g_ql + (size_t)bh * LL * 64;
#pragma unroll
        for (int it = 0; it < 8; it++) {
            int op = tid + it * 256;
            int t = op >> 10;
            int r = (op >> 3) & 127;
            int p = op & 7;
            const __nv_bfloat16* srcp = (t == 0 ? qhp : qlp) + (size_t)(q0 + r) * 64 + p * 8;
            CP_ASYNC16(sbase + t * F_QTILE + r * FROWB + p * 16, srcp);
        }
        CP_COMMIT();
    };

    auto issue_kv_for = [&](int tile, int c, int buf) {
        const int bh = tile >> 4;
        const int kt0 = c * 64;
        const __nv_bfloat16* khp = g_kh + (size_t)bh * LL * 64;
        const __nv_bfloat16* klp = g_kl + (size_t)bh * LL * 64;
        const __nv_bfloat16* vhp = g_vth + (size_t)bh * 64 * LL;
        const __nv_bfloat16* vlp = g_vtl + (size_t)bh * 64 * LL;
        const uint32_t dstb = sbase + F_KV + buf * F_KVSTRIDE;
#pragma unroll
        for (int it = 0; it < 8; it++) {
            int op = tid + it * 256;
            int t = op >> 9;
            int r = (op >> 3) & 63;
            int p = op & 7;
            const __nv_bfloat16* srcp;
            if (t == 0)      srcp = khp + (size_t)(kt0 + r) * 64 + p * 8;
            else if (t == 1) srcp = klp + (size_t)(kt0 + r) * 64 + p * 8;
            else if (t == 2) srcp = vhp + (size_t)r * LL + kt0 + p * 8;
            else             srcp = vlp + (size_t)r * LL + kt0 + p * 8;
            CP_ASYNC16(dstb + t * F_KTILE + r * FROWB + p * 16, srcp);
        }
        CP_COMMIT();
    };

    if (blockIdx.x < (unsigned)F_NTILES) {
        issue_q_for(blockIdx.x);
        issue_kv_for(blockIdx.x, 0, 0);
    }

    for (int tile = blockIdx.x; tile < F_NTILES; tile += gridDim.x) {
        const int bh = tile >> 4;
        const int b = bh >> 4;
        const int h = bh & 15;
        const int q0 = (tile & 15) * 128;

        uint32_t qfh[4][4], qfl[4][4];
        float o[8][4];
        float m_lo = -INFINITY, m_hi = -INFINITY, l_lo = 0.f, l_hi = 0.f;
#pragma unroll
        for (int i = 0; i < 8; i++)
#pragma unroll
            for (int j = 0; j < 4; j++) o[i][j] = 0.f;

        for (int c = 0; c < F_NCHUNK; c++) {
            CP_WAIT0();
            __syncthreads();
            if (c + 1 < F_NCHUNK) {
                issue_kv_for(tile, c + 1, (c + 1) & 1);
            } else if (tile + gridDim.x < F_NTILES) {
                issue_q_for(tile + gridDim.x);
                issue_kv_for(tile + gridDim.x, 0, 0);   // F_NCHUNK even -> buf 0 free
            }

            if (c == 0) {
#pragma unroll
                for (int st = 0; st < 4; st++) {
                    ldsm_x4(qfh[st], sbase + F_QH + aOff + st * 32);
                    ldsm_x4(qfl[st], sbase + F_QL + aOff + st * 32);
                }
            }

            const uint32_t kvb = sbase + F_KV + (c & 1) * F_KVSTRIDE;
            const uint32_t khB = kvb;
            const uint32_t klB = kvb + F_KTILE;
            const uint32_t vhB = kvb + 2 * F_KTILE;
            const uint32_t vlB = kvb + 3 * F_KTILE;

            // ---- S = Q K^T (3-pass) ----
            float sa[8][4];
#pragma unroll
            for (int i = 0; i < 8; i++)
#pragma unroll
                for (int j = 0; j < 4; j++) sa[i][j] = 0.f;

#pragma unroll
            for (int st = 0; st < 4; st++) {
#pragma unroll
                for (int half = 0; half < 2; half++) {
                    uint32_t kh4[2][4], kl4[2][4];
#pragma unroll
                    for (int j = 0; j < 2; j++) {
                        int nt2 = half * 2 + j;
                        ldsm_x4(kh4[j], khB + bOff + nt2 * 16 * FROWB + st * 32);
                        ldsm_x4(kl4[j], klB + bOff + nt2 * 16 * FROWB + st * 32);
                    }
#pragma unroll
                    for (int j = 0; j < 2; j++)
#pragma unroll
                        for (int hf = 0; hf < 2; hf++) {
                            int nt = (half * 2 + j) * 2 + hf;
                            mma_bf16(sa[nt], qfh[st], kh4[j][hf * 2], kh4[j][hf * 2 + 1]);
                        }
#pragma unroll
                    for (int j = 0; j < 2; j++)
#pragma unroll
                        for (int hf = 0; hf < 2; hf++) {
                            int nt = (half * 2 + j) * 2 + hf;
                            mma_bf16(sa[nt], qfh[st], kl4[j][hf * 2], kl4[j][hf * 2 + 1]);
                        }
#pragma unroll
                    for (int j = 0; j < 2; j++)
#pragma unroll
                        for (int hf = 0; hf < 2; hf++) {
                            int nt = (half * 2 + j) * 2 + hf;
                            mma_bf16(sa[nt], qfl[st], kh4[j][hf * 2], kh4[j][hf * 2 + 1]);
                        }
                }
            }

            // ---- online softmax ----
            float mxlo = -INFINITY, mxhi = -INFINITY;
#pragma unroll
            for (int nt = 0; nt < 8; nt++) {
                mxlo = fmaxf(mxlo, fmaxf(sa[nt][0], sa[nt][1]));
                mxhi = fmaxf(mxhi, fmaxf(sa[nt][2], sa[nt][3]));
            }
            mxlo = fmaxf(mxlo, __shfl_xor_sync(0xffffffffu, mxlo, 1));
            mxlo = fmaxf(mxlo, __shfl_xor_sync(0xffffffffu, mxlo, 2));
            mxhi = fmaxf(mxhi, __shfl_xor_sync(0xffffffffu, mxhi, 1));
            mxhi = fmaxf(mxhi, __shfl_xor_sync(0xffffffffu, mxhi, 2));

            float mnlo = fmaxf(m_lo, mxlo), mnhi = fmaxf(m_hi, mxhi);
            float faclo = __expf(m_lo - mnlo), fachi = __expf(m_hi - mnhi);
            m_lo = mnlo; m_hi = mnhi;

            float rslo = 0.f, rshi = 0.f;
#pragma unroll
            for (int nt = 0; nt < 8; nt++) {
                sa[nt][0] = __expf(sa[nt][0] - mnlo);
                sa[nt][1] = __expf(sa[nt][1] - mnlo);
                sa[nt][2] = __expf(sa[nt][2] - mnhi);
                sa[nt][3] = __expf(sa[nt][3] - mnhi);
                rslo += sa[nt][0] + sa[nt][1];
                rshi += sa[nt][2] + sa[nt][3];
            }
            l_lo = l_lo * faclo + rslo;
            l_hi = l_hi * fachi + rshi;
#pragma unroll
            for (int nt = 0; nt < 8; nt++) {
                o[nt][0] *= faclo; o[nt][1] *= faclo;
                o[nt][2] *= fachi; o[nt][3] *= fachi;
            }

            // ---- P -> bf16 hi/lo A-fragments ----
            uint32_t ph[4][4], pl[4][4];
#pragma unroll
            for (int t = 0; t < 4; t++) {
#pragma unroll
                for (int half = 0; half < 2; half++) {
                    int nt = 2 * t + half;
#pragma unroll
                    for (int rr = 0; rr < 2; rr++) {
                        float x = sa[nt][rr * 2], y = sa[nt][rr * 2 + 1];
                        uint32_t hp = pack_bf16(x, y);
                        __nv_bfloat162 hv = *reinterpret_cast<__nv_bfloat162*>(&hp);
                        uint32_t lp = pack_bf16(x - __bfloat162float(hv.x),
                                                y - __bfloat162float(hv.y));
                        ph[t][half * 2 + rr] = hp;
                        pl[t][half * 2 + rr] = lp;
                    }
                }
            }

            // ---- O += P @ V (3-pass) ----
#pragma unroll
            for (int t = 0; t < 4; t++) {
#pragma unroll
                for (int half = 0; half < 2; half++) {
                    uint32_t vh4[2][4], vl4[2][4];
#pragma unroll
                    for (int j = 0; j < 2; j++) {
                        int nt2 = half * 2 + j;
                        ldsm_x4(vh4[j], vhB + bOff + nt2 * 16 * FROWB + t * 32);
                        ldsm_x4(vl4[j], vlB + bOff + nt2 * 16 * FROWB + t * 32);
                    }
#pragma unroll
                    for (int j = 0; j < 2; j++)
#pragma unroll
                        for (int hf = 0; hf < 2; hf++) {
                            int nt = (half * 2 + j) * 2 + hf;
                            mma_bf16(o[nt], ph[t], vh4[j][hf * 2], vh4[j][hf * 2 + 1]);
                        }
#pragma unroll
                    for (int j = 0; j < 2; j++)
#pragma unroll
                        for (int hf = 0; hf < 2; hf++) {
                            int nt = (half * 2 + j) * 2 + hf;
                            mma_bf16(o[nt], ph[t], vl4[j][hf * 2], vl4[j][hf * 2 + 1]);
                        }
#pragma unroll
                    for (int j = 0; j < 2; j++)
#pragma unroll
                        for (int hf = 0; hf < 2; hf++) {
                            int nt = (half * 2 + j) * 2 + hf;
                            mma_bf16(o[nt], pl[t], vh4[j][hf * 2], vh4[j][hf * 2 + 1]);
                        }
                }
            }
        }

        // ---- epilogue ----
        float llo = l_lo, lhi = l_hi;
        llo += __shfl_xor_sync(0xffffffffu, llo, 1);
        llo += __shfl_xor_sync(0xffffffffu, llo, 2);
        lhi += __shfl_xor_sync(0xffffffffu, lhi, 1);
        lhi += __shfl_xor_sync(0xffffffffu, lhi, 2);
        float invlo = 1.f / llo, invhi = 1.f / lhi;

        const int rlo = wm + (lane >> 2);
        const int cb = (lane & 3) * 2;
#pragma unroll
        for (int nt = 0; nt < 8; nt++) {
            {
                size_t idx = ((size_t)(b * LL + q0 + rlo)) * DD + h * 64 + nt * 8 + cb;
                float x = o[nt][0] * invlo, y = o[nt][1] * invlo;
                __nv_bfloat162 hv, lv;
                split1(x, hv.x, lv.x); split1(y, hv.y, lv.y);
                *reinterpret_cast<__nv_bfloat162*>(&g_ah[idx]) = hv;
                *reinterpret_cast<__nv_bfloat162*>(&g_al[idx]) = lv;
            }
            {
                size_t idx = ((size_t)(b * LL + q0 + rlo + 8)) * DD + h * 64 + nt * 8 + cb;
                float x = o[nt][2] * invhi, y = o[nt][3] * invhi;
                __nv_bfloat162 hv, lv;
                split1(x, hv.x, lv.x); split1(y, hv.y, lv.y);
                *reinterpret_cast<__nv_bfloat162*>(&g_ah[idx]) = hv;
                *reinterpret_cast<__nv_bfloat162*>(&g_al[idx]) = lv;
            }
        }
    }
}

// ---------------------------------------------------------------------------
extern "C" void kernel_launch(void* const* d_in, const int* in_sizes, int n_in,
                              void* d_out, int out_size)
{
    const float* x     = (const float*)d_in[0];
    const float* cosT  = (const float*)d_in[1];
    const float* sinT  = (const float*)d_in[2];
    const float* w_qkv = (const float*)d_in[3];
    const float* w_o   = (const float*)d_in[4];
    float* out = (float*)d_out;

    float* qkv_ptr;
    __nv_bfloat16 *xh, *xl, *wqh, *wql, *woh, *wol, *ah, *al;
    cudaGetSymbolAddress((void**)&qkv_ptr, g_qkv);
    cudaGetSymbolAddress((void**)&xh, g_xh);   cudaGetSymbolAddress((void**)&xl, g_xl);
    cudaGetSymbolAddress((void**)&wqh, g_wqh); cudaGetSymbolAddress((void**)&wql, g_wql);
    cudaGetSymbolAddress((void**)&woh, g_woh); cudaGetSymbolAddress((void**)&wol, g_wol);
    cudaGetSymbolAddress((void**)&ah, g_ah);   cudaGetSymbolAddress((void**)&al, g_al);

    cudaFuncSetAttribute(gemm_mma_kernel,
                         cudaFuncAttributeMaxDynamicSharedMemorySize, GEMM_SMEM_DYN);
    cudaFuncSetAttribute(flash_mma_kernel,
                         cudaFuncAttributeMaxDynamicSharedMemorySize, FLASH_SMEM);

    // 0. fused bf16 splits of x, w_qkv, w_o (one launch)
    fused_split_kernel<<<(N4_TOT + 255) / 256, 256>>>(x, w_qkv, w_o);

    // 1. QKV projection (persistent + cross-tile prefetch)
    gemm_mma_kernel<<<NPERS, 512, GEMM_SMEM_DYN>>>(xh, xl, wqh, wql, qkv_ptr,
                                                   ML, 3 * DD, DD);
    // 2. RoPE + bf16 split (q scaled by 1/8) + V transpose
    {
        dim3 grid(LL / 64, BB * HH);
        rope_split_kernel<<<grid, 256>>>(cosT, sinT);
    }
    // 3. Flash attention (persistent + cross-tile prefetch)
    flash_mma_kernel<<<NPERS, 256, FLASH_SMEM>>>();

    // 4. Output projection (persistent + cross-tile prefetch)
    gemm_mma_kernel<<<NPERS, 512, GEMM_SMEM_DYN>>>(ah, al, woh, wol, out,
                                                   ML, DD, DD);
}

// round 17
// speedup vs baseline: 1.4366x; 1.3827x over previous
#include <cuda_runtime.h>
#include <cuda_fp16.h>
#include <math.h>
#include <cstdint>

#define BB 2
#define LL 2048
#define DD 1024
#define HH 16
#define DH 64
#define ML (BB*LL)          // 4096 rows
#define NPERS 296

// ---------------------------------------------------------------------------
// Scratch (allocation-free rule: device globals)
// ---------------------------------------------------------------------------
__device__ float g_qkv[ML * 3 * DD];        // [b,l,3,h,dh] fp32 (QKV gemm out)

// fp16 flash operands (written by rope kernel)
__device__ __half g_qh[BB*HH*LL*DH], g_ql[BB*HH*LL*DH];  // [bh][l][d], pre-scaled 1/8, split
__device__ __half g_k [BB*HH*LL*DH];                     // [bh][l][d], single fp16
__device__ __half g_vt[BB*HH*DH*LL];                     // [bh][d][l], single fp16

// fp16 GEMM operands
__device__ __half g_xh[ML * DD], g_xl[ML * DD];          // x split
__device__ __half g_wq[3 * DD * DD];                     // w_qkv single
__device__ __half g_wo[DD * DD];                         // w_o single
__device__ __half g_ah[ML * DD], g_al[ML * DD];          // flash out split

// ---------------------------------------------------------------------------
// PTX helpers (sm_100-safe)
// ---------------------------------------------------------------------------
__device__ __forceinline__ uint32_t smem_u32(const void* p) {
    uint32_t a;
    asm("{ .reg .u64 t; cvta.to.shared.u64 t, %1; cvt.u32.u64 %0, t; }" : "=r"(a) : "l"(p));
    return a;
}
#define CP_ASYNC16(dst, src) \
    asm volatile("cp.async.cg.shared.global [%0], [%1], 16;" :: "r"(dst), "l"(src))
#define CP_COMMIT()  asm volatile("cp.async.commit_group;")
#define CP_WAIT0()   asm volatile("cp.async.wait_group 0;" ::: "memory")

__device__ __forceinline__ void ldsm_x4(uint32_t* r, uint32_t addr) {
    asm volatile("ldmatrix.sync.aligned.m8n8.x4.shared.b16 {%0,%1,%2,%3}, [%4];"
                 : "=r"(r[0]), "=r"(r[1]), "=r"(r[2]), "=r"(r[3]) : "r"(addr));
}
__device__ __forceinline__ void mma_f16(float* d, const uint32_t* a,
                                        uint32_t b0, uint32_t b1) {
    asm volatile(
        "mma.sync.aligned.m16n8k16.row.col.f32.f16.f16.f32 "
        "{%0,%1,%2,%3}, {%4,%5,%6,%7}, {%8,%9}, {%0,%1,%2,%3};"
        : "+f"(d[0]), "+f"(d[1]), "+f"(d[2]), "+f"(d[3])
        : "r"(a[0]), "r"(a[1]), "r"(a[2]), "r"(a[3]), "r"(b0), "r"(b1));
}

__device__ __forceinline__ void split1h(float x, __half& h, __half& l) {
    h = __float2half_rn(x);
    l = __float2half_rn(x - __half2float(h));
}
__device__ __forceinline__ uint32_t pack_h2(float x, float y) {
    __half2 t;
    t.x = __float2half_rn(x);
    t.y = __float2half_rn(y);
    return *reinterpret_cast<uint32_t*>(&t);
}

// ---------------------------------------------------------------------------
// Fused split/convert: x -> (xh,xl); wq -> fp16; wo -> fp16. One launch.
// ---------------------------------------------------------------------------
#define N4_X   (ML * DD / 4)
#define N4_WQ  (3 * DD * DD / 4)
#define N4_WO  (DD * DD / 4)
#define N4_TOT (N4_X + N4_WQ + N4_WO)

__global__ __launch_bounds__(256) void fused_split_kernel(
    const float* __restrict__ x, const float* __restrict__ wq,
    const float* __restrict__ wo)
{
    int i = blockIdx.x * blockDim.x + threadIdx.x;
    if (i >= N4_TOT) return;
    if (i < N4_X) {
        float4 v = reinterpret_cast<const float4*>(x)[i];
        __half2 hh0, hh1, ll0, ll1;
        split1h(v.x, hh0.x, ll0.x); split1h(v.y, hh0.y, ll0.y);
        split1h(v.z, hh1.x, ll1.x); split1h(v.w, hh1.y, ll1.y);
        reinterpret_cast<__half2*>(g_xh)[i * 2]     = hh0;
        reinterpret_cast<__half2*>(g_xh)[i * 2 + 1] = hh1;
        reinterpret_cast<__half2*>(g_xl)[i * 2]     = ll0;
        reinterpret_cast<__half2*>(g_xl)[i * 2 + 1] = ll1;
    } else {
        const float* src;
        __half* dst;
        int idx;
        if (i < N4_X + N4_WQ) { src = wq; dst = g_wq; idx = i - N4_X; }
        else                  { src = wo; dst = g_wo; idx = i - N4_X - N4_WQ; }
        float4 v = reinterpret_cast<const float4*>(src)[idx];
        __half2 h0 = {__float2half_rn(v.x), __float2half_rn(v.y)};
        __half2 h1 = {__float2half_rn(v.z), __float2half_rn(v.w)};
        reinterpret_cast<__half2*>(dst)[idx * 2]     = h0;
        reinterpret_cast<__half2*>(dst)[idx * 2 + 1] = h1;
    }
}

// ---------------------------------------------------------------------------
// fp16x2 GEMM: C[M,N] = (Ah+Al)[M,K] @ W[N,K]^T, 2 passes.
// 512 threads, 16 warps 4x4, 128x128 tile, K-chunk 32, persistent + prefetch.
// 3 smem tiles per buffer (Ah, Al, W).
// ---------------------------------------------------------------------------
#define KC 32
#define ROWB 80
#define TILE_B (128 * ROWB)
#define BUF_B  (3 * TILE_B)
#define GEMM_SMEM_DYN (2 * BUF_B)

__global__ __launch_bounds__(512, 2) void gemm_mma_kernel(
    const __half* __restrict__ Ah, const __half* __restrict__ Al,
    const __half* __restrict__ W,
    float* __restrict__ C, int M, int N, int K)
{
    extern __shared__ uint8_t sm8[];
    const uint32_t sbase = smem_u32(sm8);

    const int tid  = threadIdx.x;
    const int wid  = tid >> 5;
    const int lane = tid & 31;
    const int wm = (wid & 3) * 32;
    const int wn = (wid >> 2) * 32;

    const uint32_t aOff = (uint32_t)((wm + (lane & 15)) * ROWB + (lane >> 4) * 16);
    const uint32_t bOff = (uint32_t)((wn + (lane & 7) + ((lane >> 4) << 3)) * ROWB
                                     + ((lane >> 3) & 1) * 16);
    const int nc = K / KC;                 // 32 (even)
    const int ntn = N >> 7;
    const int ntiles = (M >> 7) * ntn;

    auto issue_for = [&](int tile, int c, int buf) {
        const int m0 = (tile / ntn) * 128;
        const int n0 = (tile % ntn) * 128;
        const int kc = c * KC;
        const uint32_t dstb = sbase + buf * BUF_B;
#pragma unroll
        for (int it = 0; it < 3; it++) {
            int op = tid + it * 512;      // 0..1535
            int t = op >> 9;              // 0=Ah 1=Al 2=W
            int r = (op >> 2) & 127;
            int p = op & 3;
            const __half* srcp;
            if (t == 0)      srcp = Ah + (size_t)(m0 + r) * K + kc + p * 8;
            else if (t == 1) srcp = Al + (size_t)(m0 + r) * K + kc + p * 8;
            else             srcp = W  + (size_t)(n0 + r) * K + kc + p * 8;
            CP_ASYNC16(dstb + t * TILE_B + r * ROWB + p * 16, srcp);
        }
        CP_COMMIT();
    };

    if (blockIdx.x < (unsigned)ntiles) issue_for(blockIdx.x, 0, 0);

    for (int tile = blockIdx.x; tile < ntiles; tile += gridDim.x) {
        const int m0 = (tile / ntn) * 128;
        const int n0 = (tile % ntn) * 128;

        float acc[2][4][4];
#pragma unroll
        for (int i = 0; i < 2; i++)
#pragma unroll
            for (int j = 0; j < 4; j++)
#pragma unroll
                for (int q = 0; q < 4; q++) acc[i][j][q] = 0.f;

        for (int c = 0; c < nc; c++) {
            CP_WAIT0();
            __syncthreads();
            if (c + 1 < nc) {
                issue_for(tile, c + 1, (c + 1) & 1);
            } else if (tile + gridDim.x < ntiles) {
                issue_for(tile + gridDim.x, 0, 0);
            }

            const uint32_t dstb = sbase + (c & 1) * BUF_B;
#pragma unroll
            for (int step = 0; step < 2; step++) {
                uint32_t aFh[2][4], aFl[2][4];
#pragma unroll
                for (int mt = 0; mt < 2; mt++) {
                    ldsm_x4(aFh[mt], dstb + aOff + mt * 16 * ROWB + step * 32);
                    ldsm_x4(aFl[mt], dstb + TILE_B + aOff + mt * 16 * ROWB + step * 32);
                }
                uint32_t bF[8];
#pragma unroll
                for (int nt2 = 0; nt2 < 2; nt2++)
                    ldsm_x4(bF + nt2 * 4, dstb + 2 * TILE_B + bOff + nt2 * 16 * ROWB + step * 32);
                // pass 1: Ah W (8 independent accs)
#pragma unroll
                for (int mt = 0; mt < 2; mt++)
#pragma unroll
                    for (int nt = 0; nt < 4; nt++) {
                        int bi = (nt >> 1) * 4 + (nt & 1) * 2;
                        mma_f16(acc[mt][nt], aFh[mt], bF[bi], bF[bi + 1]);
                    }
                // pass 2: Al W
#pragma unroll
                for (int mt = 0; mt < 2; mt++)
#pragma unroll
                    for (int nt = 0; nt < 4; nt++) {
                        int bi = (nt >> 1) * 4 + (nt & 1) * 2;
                        mma_f16(acc[mt][nt], aFl[mt], bF[bi], bF[bi + 1]);
                    }
            }
        }

        const int rb = lane >> 2;
        const int cb = (lane & 3) * 2;
#pragma unroll
        for (int mt = 0; mt < 2; mt++)
#pragma unroll
            for (int nt = 0; nt < 4; nt++) {
                int row = m0 + wm + mt * 16 + rb;
                int col = n0 + wn + nt * 8 + cb;
                *reinterpret_cast<float2*>(&C[(size_t)row * N + col]) =
                    make_float2(acc[mt][nt][0], acc[mt][nt][1]);
                *reinterpret_cast<float2*>(&C[(size_t)(row + 8) * N + col]) =
                    make_float2(acc[mt][nt][2], acc[mt][nt][3]);
            }
    }
}

// ---------------------------------------------------------------------------
// RoPE + fp16 convert. Q pre-scaled 1/8 then SPLIT (qh,ql); K,V single fp16.
// V transposed to [bh][d][l].
// ---------------------------------------------------------------------------
__global__ __launch_bounds__(256) void rope_split_kernel(
    const float* __restrict__ cosT, const float* __restrict__ sinT)
{
    __shared__ float Vs[64][65];

    const int tid = threadIdx.x;
    const int bh = blockIdx.y;
    const int b = bh >> 4;
    const int h = bh & 15;
    const int l0 = blockIdx.x * 64;

#pragma unroll
    for (int it = 0; it < 8; it++) {
        int p = tid + it * 256;
        int l = p >> 5;
        int i = p & 31;
        int lg = l0 + l;
        size_t base = ((size_t)(b * LL + lg) * 3) * DD + h * 64;
        float c0 = cosT[lg * 64 + i],      s0 = sinT[lg * 64 + i];
        float c1 = cosT[lg * 64 + i + 32], s1 = sinT[lg * 64 + i + 32];
        size_t qi = ((size_t)bh * LL + lg) * 64;

        float q1 = g_qkv[base + i], q2 = g_qkv[base + i + 32];
        float qa = (q1 * c0 - q2 * s0) * 0.125f;
        float qb = (q2 * c1 + q1 * s1) * 0.125f;
        __half hh, ll;
        split1h(qa, hh, ll); g_qh[qi + i] = hh;      g_ql[qi + i] = ll;
        split1h(qb, hh, ll); g_qh[qi + i + 32] = hh; g_ql[qi + i + 32] = ll;

        float k1 = g_qkv[base + DD + i], k2 = g_qkv[base + DD + i + 32];
        g_k[qi + i]      = __float2half_rn(k1 * c0 - k2 * s0);
        g_k[qi + i + 32] = __float2half_rn(k2 * c1 + k1 * s1);
    }

#pragma unroll
    for (int it = 0; it < 4; it++) {
        int f = tid + it * 256;
        int r = f >> 4;
        int dq = (f & 15) * 4;
        float4 vv = *reinterpret_cast<const float4*>(
            &g_qkv[((size_t)(b * LL + l0 + r) * 3 + 2) * DD + h * 64 + dq]);
        Vs[r][dq] = vv.x; Vs[r][dq + 1] = vv.y; Vs[r][dq + 2] = vv.z; Vs[r][dq + 3] = vv.w;
    }
    __syncthreads();
#pragma unroll
    for (int it = 0; it < 4; it++) {
        int f = tid + it * 256;
        int d = f >> 4;
        int lq = (f & 15) * 4;
        size_t vi = ((size_t)(bh * 64 + d)) * LL + l0 + lq;
        __half2 a = {__float2half_rn(Vs[lq][d]),     __float2half_rn(Vs[lq + 1][d])};
        __half2 bq = {__float2half_rn(Vs[lq + 2][d]), __float2half_rn(Vs[lq + 3][d])};
        *reinterpret_cast<__half2*>(&g_vt[vi])     = a;
        *reinterpret_cast<__half2*>(&g_vt[vi + 2]) = bq;
    }
}

// ---------------------------------------------------------------------------
// Flash attention fp16x2, 2-pass. Persistent + cross-tile prefetch.
// smem: Qh/Ql [128][144]; double-buffered K,V [64][144] each.
// ---------------------------------------------------------------------------
#define FROWB 144
#define F_QTILE (128 * FROWB)             // 18432
#define F_KTILE (64 * FROWB)              // 9216
#define F_QH 0
#define F_QL F_QTILE
#define F_KV (2 * F_QTILE)                // 36864
#define F_KVSTRIDE (2 * F_KTILE)          // 18432 per buffer (K + V)
#define FLASH_SMEM (F_KV + 2 * F_KVSTRIDE)  // 73728
#define F_NTILES ((LL / 128) * BB * HH)   // 512
#define F_NCHUNK (LL / 64)                // 32 (even)

__global__ __launch_bounds__(256, 2) void flash_mma_kernel()
{
    extern __shared__ uint8_t sm8[];
    const uint32_t sbase = smem_u32(sm8);

    const int tid  = threadIdx.x;
    const int wid  = tid >> 5;
    const int lane = tid & 31;
    const int wm = wid * 16;

    const uint32_t aOff = (uint32_t)((wm + (lane & 15)) * FROWB + (lane >> 4) * 16);
    const uint32_t bOff = (uint32_t)(((lane & 7) + ((lane >> 4) << 3)) * FROWB
                                     + ((lane >> 3) & 1) * 16);

    auto issue_q_for = [&](int tile) {
        const int bh = tile >> 4;
        const int q0 = (tile & 15) * 128;
        const __half* qhp = g_qh + (size_t)bh * LL * 64;
        const __half* qlp = g_ql + (size_t)bh * LL * 64;
#pragma unroll
        for (int it = 0; it < 8; it++) {
            int op = tid + it * 256;
            int t = op >> 10;
            int r = (op >> 3) & 127;
            int p = op & 7;
            const __half* srcp = (t == 0 ? qhp : qlp) + (size_t)(q0 + r) * 64 + p * 8;
            CP_ASYNC16(sbase + t * F_QTILE + r * FROWB + p * 16, srcp);
        }
        CP_COMMIT();
    };

    auto issue_kv_for = [&](int tile, int c, int buf) {
        const int bh = tile >> 4;
        const int kt0 = c * 64;
        const __half* kp = g_k  + (size_t)bh * LL * 64;
        const __half* vp = g_vt + (size_t)bh * 64 * LL;
        const uint32_t dstb = sbase + F_KV + buf * F_KVSTRIDE;
#pragma unroll
        for (int it = 0; it < 4; it++) {
            int op = tid + it * 256;      // 0..1023
            int t = op >> 9;              // 0=K 1=V
            int r = (op >> 3) & 63;
            int p = op & 7;
            const __half* srcp;
            if (t == 0) srcp = kp + (size_t)(kt0 + r) * 64 + p * 8;
            else        srcp = vp + (size_t)r * LL + kt0 + p * 8;
            CP_ASYNC16(dstb + t * F_KTILE + r * FROWB + p * 16, srcp);
        }
        CP_COMMIT();
    };

    if (blockIdx.x < (unsigned)F_NTILES) {
        issue_q_for(blockIdx.x);
        issue_kv_for(blockIdx.x, 0, 0);
    }

    for (int tile = blockIdx.x; tile < F_NTILES; tile += gridDim.x) {
        const int bh = tile >> 4;
        const int b = bh >> 4;
        const int h = bh & 15;
        const int q0 = (tile & 15) * 128;

        uint32_t qfh[4][4], qfl[4][4];
        float o[8][4];
        float m_lo = -INFINITY, m_hi = -INFINITY, l_lo = 0.f, l_hi = 0.f;
#pragma unroll
        for (int i = 0; i < 8; i++)
#pragma unroll
            for (int j = 0; j < 4; j++) o[i][j] = 0.f;

        for (int c = 0; c < F_NCHUNK; c++) {
            CP_WAIT0();
            __syncthreads();
            if (c + 1 < F_NCHUNK) {
                issue_kv_for(tile, c + 1, (c + 1) & 1);
            } else if (tile + gridDim.x < F_NTILES) {
                issue_q_for(tile + gridDim.x);
                issue_kv_for(tile + gridDim.x, 0, 0);
            }

            if (c == 0) {
#pragma unroll
                for (int st = 0; st < 4; st++) {
                    ldsm_x4(qfh[st], sbase + F_QH + aOff + st * 32);
                    ldsm_x4(qfl[st], sbase + F_QL + aOff + st * 32);
                }
            }

            const uint32_t kvb = sbase + F_KV + (c & 1) * F_KVSTRIDE;
            const uint32_t kB = kvb;
            const uint32_t vB = kvb + F_KTILE;

            // ---- S = (Qh+Ql) K^T, 2-pass ----
            float sa[8][4];
#pragma unroll
            for (int i = 0; i < 8; i++)
#pragma unroll
                for (int j = 0; j < 4; j++) sa[i][j] = 0.f;

#pragma unroll
            for (int st = 0; st < 4; st++) {
#pragma unroll
                for (int half = 0; half < 2; half++) {
                    uint32_t k4[2][4];
#pragma unroll
                    for (int j = 0; j < 2; j++) {
                        int nt2 = half * 2 + j;
                        ldsm_x4(k4[j], kB + bOff + nt2 * 16 * FROWB + st * 32);
                    }
#pragma unroll
                    for (int j = 0; j < 2; j++)
#pragma unroll
                        for (int hf = 0; hf < 2; hf++) {
                            int nt = (half * 2 + j) * 2 + hf;
                            mma_f16(sa[nt], qfh[st], k4[j][hf * 2], k4[j][hf * 2 + 1]);
                        }
#pragma unroll
                    for (int j = 0; j < 2; j++)
#pragma unroll
                        for (int hf = 0; hf < 2; hf++) {
                            int nt = (half * 2 + j) * 2 + hf;
                            mma_f16(sa[nt], qfl[st], k4[j][hf * 2], k4[j][hf * 2 + 1]);
                        }
                }
            }

            // ---- online softmax ----
            float mxlo = -INFINITY, mxhi = -INFINITY;
#pragma unroll
            for (int nt = 0; nt < 8; nt++) {
                mxlo = fmaxf(mxlo, fmaxf(sa[nt][0], sa[nt][1]));
                mxhi = fmaxf(mxhi, fmaxf(sa[nt][2], sa[nt][3]));
            }
            mxlo = fmaxf(mxlo, __shfl_xor_sync(0xffffffffu, mxlo, 1));
            mxlo = fmaxf(mxlo, __shfl_xor_sync(0xffffffffu, mxlo, 2));
            mxhi = fmaxf(mxhi, __shfl_xor_sync(0xffffffffu, mxhi, 1));
            mxhi = fmaxf(mxhi, __shfl_xor_sync(0xffffffffu, mxhi, 2));

            float mnlo = fmaxf(m_lo, mxlo), mnhi = fmaxf(m_hi, mxhi);
            float faclo = __expf(m_lo - mnlo), fachi = __expf(m_hi - mnhi);
            m_lo = mnlo; m_hi = mnhi;

            float rslo = 0.f, rshi = 0.f;
#pragma unroll
            for (int nt = 0; nt < 8; nt++) {
                sa[nt][0] = __expf(sa[nt][0] - mnlo);
                sa[nt][1] = __expf(sa[nt][1] - mnlo);
                sa[nt][2] = __expf(sa[nt][2] - mnhi);
                sa[nt][3] = __expf(sa[nt][3] - mnhi);
                rslo += sa[nt][0] + sa[nt][1];
                rshi += sa[nt][2] + sa[nt][3];
            }
            l_lo = l_lo * faclo + rslo;
            l_hi = l_hi * fachi + rshi;
#pragma unroll
            for (int nt = 0; nt < 8; nt++) {
                o[nt][0] *= faclo; o[nt][1] *= faclo;
                o[nt][2] *= fachi; o[nt][3] *= fachi;
            }

            // ---- P -> fp16 hi/lo A-fragments ----
            uint32_t ph[4][4], pl[4][4];
#pragma unroll
            for (int t = 0; t < 4; t++) {
#pragma unroll
                for (int half = 0; half < 2; half++) {
                    int nt = 2 * t + half;
#pragma unroll
                    for (int rr = 0; rr < 2; rr++) {
                        float x = sa[nt][rr * 2], y = sa[nt][rr * 2 + 1];
                        uint32_t hp = pack_h2(x, y);
                        __half2 hv = *reinterpret_cast<__half2*>(&hp);
                        uint32_t lp = pack_h2(x - __half2float(hv.x),
                                              y - __half2float(hv.y));
                        ph[t][half * 2 + rr] = hp;
                        pl[t][half * 2 + rr] = lp;
                    }
                }
            }

            // ---- O += (Ph+Pl) V, 2-pass ----
#pragma unroll
            for (int t = 0; t < 4; t++) {
#pragma unroll
                for (int half = 0; half < 2; half++) {
                    uint32_t v4[2][4];
#pragma unroll
                    for (int j = 0; j < 2; j++) {
                        int nt2 = half * 2 + j;
                        ldsm_x4(v4[j], vB + bOff + nt2 * 16 * FROWB + t * 32);
                    }
#pragma unroll
                    for (int j = 0; j < 2; j++)
#pragma unroll
                        for (int hf = 0; hf < 2; hf++) {
                            int nt = (half * 2 + j) * 2 + hf;
                            mma_f16(o[nt], ph[t], v4[j][hf * 2], v4[j][hf * 2 + 1]);
                        }
#pragma unroll
                    for (int j = 0; j < 2; j++)
#pragma unroll
                        for (int hf = 0; hf < 2; hf++) {
                            int nt = (half * 2 + j) * 2 + hf;
                            mma_f16(o[nt], pl[t], v4[j][hf * 2], v4[j][hf * 2 + 1]);
                        }
                }
            }
        }

        // ---- epilogue: normalize, write fp16 hi/lo to g_ah/g_al ----
        float llo = l_lo, lhi = l_hi;
        llo += __shfl_xor_sync(0xffffffffu, llo, 1);
        llo += __shfl_xor_sync(0xffffffffu, llo, 2);
        lhi += __shfl_xor_sync(0xffffffffu, lhi, 1);
        lhi += __shfl_xor_sync(0xffffffffu, lhi, 2);
        float invlo = 1.f / llo, invhi = 1.f / lhi;

        const int rlo = wm + (lane >> 2);
        const int cb = (lane & 3) * 2;
#pragma unroll
        for (int nt = 0; nt < 8; nt++) {
            {
                size_t idx = ((size_t)(b * LL + q0 + rlo)) * DD + h * 64 + nt * 8 + cb;
                float x = o[nt][0] * invlo, y = o[nt][1] * invlo;
                __half2 hv, lv;
                split1h(x, hv.x, lv.x); split1h(y, hv.y, lv.y);
                *reinterpret_cast<__half2*>(&g_ah[idx]) = hv;
                *reinterpret_cast<__half2*>(&g_al[idx]) = lv;
            }
            {
                size_t idx = ((size_t)(b * LL + q0 + rlo + 8)) * DD + h * 64 + nt * 8 + cb;
                float x = o[nt][2] * invhi, y = o[nt][3] * invhi;
                __half2 hv, lv;
                split1h(x, hv.x, lv.x); split1h(y, hv.y, lv.y);
                *reinterpret_cast<__half2*>(&g_ah[idx]) = hv;
                *reinterpret_cast<__half2*>(&g_al[idx]) = lv;
            }
        }
    }
}

// ---------------------------------------------------------------------------
extern "C" void kernel_launch(void* const* d_in, const int* in_sizes, int n_in,
                              void* d_out, int out_size)
{
    const float* x     = (const float*)d_in[0];
    const float* cosT  = (const float*)d_in[1];
    const float* sinT  = (const float*)d_in[2];
    const float* w_qkv = (const float*)d_in[3];
    const float* w_o   = (const float*)d_in[4];
    float* out = (float*)d_out;

    float* qkv_ptr;
    __half *xh, *xl, *wq, *wo, *ah, *al;
    cudaGetSymbolAddress((void**)&qkv_ptr, g_qkv);
    cudaGetSymbolAddress((void**)&xh, g_xh); cudaGetSymbolAddress((void**)&xl, g_xl);
    cudaGetSymbolAddress((void**)&wq, g_wq); cudaGetSymbolAddress((void**)&wo, g_wo);
    cudaGetSymbolAddress((void**)&ah, g_ah); cudaGetSymbolAddress((void**)&al, g_al);

    cudaFuncSetAttribute(gemm_mma_kernel,
                         cudaFuncAttributeMaxDynamicSharedMemorySize, GEMM_SMEM_DYN);
    cudaFuncSetAttribute(flash_mma_kernel,
                         cudaFuncAttributeMaxDynamicSharedMemorySize, FLASH_SMEM);

    // 0. fused fp16 conversions
    fused_split_kernel<<<(N4_TOT + 255) / 256, 256>>>(x, w_qkv, w_o);

    // 1. QKV projection (fp16x2, 2-pass, persistent)
    gemm_mma_kernel<<<NPERS, 512, GEMM_SMEM_DYN>>>(xh, xl, wq, qkv_ptr,
                                                   ML, 3 * DD, DD);
    // 2. RoPE + fp16 convert (q split + scaled, k/v single)
    {
        dim3 grid(LL / 64, BB * HH);
        rope_split_kernel<<<grid, 256>>>(cosT, sinT);
    }
    // 3. Flash attention (fp16x2, 2-pass, persistent)
    flash_mma_kernel<<<NPERS, 256, FLASH_SMEM>>>();

    // 4. Output projection (fp16x2, 2-pass, persistent)
    gemm_mma_kernel<<<NPERS, 512, GEMM_SMEM_DYN>>>(ah, al, wo, out,
                                                   ML, DD, DD);
}